// round 10
// baseline (speedup 1.0000x reference)
#include <cuda_runtime.h>
#include <cuda_bf16.h>
#include <math.h>
#include <cstdint>

// ---------------------------------------------------------------------------
// TemporalMamba: B=2, L=1024, D_MODEL=1024, D_INNER=2048, D_STATE=16,
// D_CONV=4, DT_RANK=64.
// Tensor cores via mma.sync.m16n8k16 bf16x3 split (toolchain is compute_100
// base: tcgen05 unavailable).
// ---------------------------------------------------------------------------

#define BB       2
#define LL       1024
#define DMODEL   1024
#define DINNER   2048
#define DSTATE   16
#define DTRANK   64
#define MROWS    (BB * LL)                  // 2048
#define XPROJ_N  (DTRANK + 2 * DSTATE)      // 96
#define KSPLITS  8

// ------------------------- scratch (device globals) ------------------------
__device__ float g_xz[MROWS * 2 * DINNER];      // [M, 4096]
__device__ float g_u[MROWS * DINNER];           // [M, 2048]
__device__ float g_xpart[KSPLITS * MROWS * XPROJ_N];  // xproj split-K partials
__device__ float g_part[2 * MROWS * DMODEL];    // GEMM4 split-K partials

// bf16 split operands
__device__ __nv_bfloat16 g_xh[MROWS * DMODEL];
__device__ __nv_bfloat16 g_xl[MROWS * DMODEL];
__device__ __nv_bfloat16 g_winT_h[4096 * DMODEL];
__device__ __nv_bfloat16 g_winT_l[4096 * DMODEL];
__device__ __nv_bfloat16 g_yh[MROWS * DINNER];
__device__ __nv_bfloat16 g_yl[MROWS * DINNER];
__device__ __nv_bfloat16 g_woutT_h[DMODEL * DINNER];
__device__ __nv_bfloat16 g_woutT_l[DMODEL * DINNER];

// ---------------------------------------------------------------------------
// mma.sync / ldmatrix / cp.async helpers
// ---------------------------------------------------------------------------
__device__ __forceinline__ uint32_t smem_u32(const void* p) {
    uint32_t a;
    asm("{ .reg .u64 t; cvta.to.shared.u64 t, %1; cvt.u32.u64 %0, t; }" : "=r"(a) : "l"(p));
    return a;
}
__device__ __forceinline__ void cpa16(uint32_t s, const void* g) {
    asm volatile("cp.async.cg.shared.global [%0], [%1], 16;" :: "r"(s), "l"(g));
}
__device__ __forceinline__ void ldsm4(uint32_t& r0, uint32_t& r1, uint32_t& r2, uint32_t& r3,
                                      uint32_t addr) {
    asm volatile("ldmatrix.sync.aligned.m8n8.x4.shared.b16 {%0,%1,%2,%3}, [%4];"
                 : "=r"(r0), "=r"(r1), "=r"(r2), "=r"(r3) : "r"(addr));
}
__device__ __forceinline__ void mma16816(float& c0, float& c1, float& c2, float& c3,
                                         uint32_t a0, uint32_t a1, uint32_t a2, uint32_t a3,
                                         uint32_t b0, uint32_t b1) {
    asm volatile(
        "mma.sync.aligned.m16n8k16.row.col.f32.bf16.bf16.f32 "
        "{%0,%1,%2,%3}, {%4,%5,%6,%7}, {%8,%9}, {%0,%1,%2,%3};"
        : "+f"(c0), "+f"(c1), "+f"(c2), "+f"(c3)
        : "r"(a0), "r"(a1), "r"(a2), "r"(a3), "r"(b0), "r"(b1));
}

// ---------------------------------------------------------------------------
// bf16x3 split tensor-core GEMM:  C[M,N] = (Ah+Al)[M,K] @ (Bh+Bl)^T
//   A row-major [M][K], B as Bt[N][K] (K-major).  CTA: 256 thr = 8 warps
//   (2 M x 4 N), tile 128x128, warp tile 64x32, BK=32, cp.async double
//   buffer, 2 CTAs/SM.  Terms: AhBh + AhBl + AlBh, fp32 accumulate.
//   gridDim.z splits K deterministically; z writes C + z*partStride.
// ---------------------------------------------------------------------------
#define SSTR     40                                  // smem row stride (bf16)
#define TILE_B   (128 * SSTR * 2)                    // 10240 B per tile
#define STAGE_B  (4 * TILE_B)                        // Ah, Al, Bh, Bl
#define GM_SMEM  (2 * STAGE_B)                       // 81920 B

__device__ __forceinline__ void load_stage_tile(
    const __nv_bfloat16* __restrict__ G, int rowBase, int k0, int K,
    uint32_t sdst, int tid)
{
#pragma unroll
    for (int i = 0; i < 2; i++) {
        int idx = tid + i * 256;            // 0..511
        int r = idx >> 2;                   // row 0..127
        int q = idx & 3;                    // 16B chunk in 64B row
        const void* g = G + (size_t)(rowBase + r) * K + k0 + q * 8;
        cpa16(sdst + (uint32_t)(r * SSTR + q * 8) * 2, g);
    }
}

__global__ __launch_bounds__(256, 2)
void gemm_mma(const __nv_bfloat16* __restrict__ Ah, const __nv_bfloat16* __restrict__ Al,
              const __nv_bfloat16* __restrict__ Bh, const __nv_bfloat16* __restrict__ Bl,
              float* __restrict__ C, int Kfull, int ldc, int kdepth,
              size_t partStride)
{
    extern __shared__ __align__(16) char dsm[];
    const uint32_t sbase = smem_u32(dsm);

    const int tid  = threadIdx.x;
    const int wid  = tid >> 5;
    const int lane = tid & 31;
    const int wm   = wid >> 2;              // 0..1  (M)
    const int wn   = wid & 3;               // 0..3  (N)
    const int bx   = blockIdx.x, by = blockIdx.y;
    const int kbase = blockIdx.z * kdepth;
    C += (size_t)blockIdx.z * partStride;

    const int aRow  = lane & 15;
    const int aCsel = (lane >> 4) * 8;
    const int bRow  = (lane & 7) + ((lane >> 4) << 3);
    const int bCsel = ((lane >> 3) & 1) * 8;

    float acc[4][4][4];
#pragma unroll
    for (int i = 0; i < 4; i++)
#pragma unroll
        for (int j = 0; j < 4; j++)
#pragma unroll
            for (int v = 0; v < 4; v++) acc[i][j][v] = 0.f;

    const int NC = kdepth >> 5;

    load_stage_tile(Ah, by * 128, kbase, Kfull, sbase + 0 * TILE_B, tid);
    load_stage_tile(Al, by * 128, kbase, Kfull, sbase + 1 * TILE_B, tid);
    load_stage_tile(Bh, bx * 128, kbase, Kfull, sbase + 2 * TILE_B, tid);
    load_stage_tile(Bl, bx * 128, kbase, Kfull, sbase + 3 * TILE_B, tid);
    asm volatile("cp.async.commit_group;");

    for (int c = 0; c < NC; c++) {
        if (c + 1 < NC) {
            const uint32_t sd = sbase + ((c + 1) & 1) * STAGE_B;
            const int k0 = kbase + ((c + 1) << 5);
            load_stage_tile(Ah, by * 128, k0, Kfull, sd + 0 * TILE_B, tid);
            load_stage_tile(Al, by * 128, k0, Kfull, sd + 1 * TILE_B, tid);
            load_stage_tile(Bh, bx * 128, k0, Kfull, sd + 2 * TILE_B, tid);
            load_stage_tile(Bl, bx * 128, k0, Kfull, sd + 3 * TILE_B, tid);
            asm volatile("cp.async.commit_group;");
            asm volatile("cp.async.wait_group 1;");
        } else {
            asm volatile("cp.async.wait_group 0;");
        }
        __syncthreads();

        const uint32_t st = sbase + (c & 1) * STAGE_B;
        const uint32_t sAh = st + 0 * TILE_B;
        const uint32_t sAl = st + 1 * TILE_B;
        const uint32_t sBh = st + 2 * TILE_B;
        const uint32_t sBl = st + 3 * TILE_B;

#pragma unroll
        for (int kk = 0; kk < 32; kk += 16) {
            uint32_t ah[4][4], al[4][4], bh[2][4], bl[2][4];
#pragma unroll
            for (int i = 0; i < 4; i++) {
                uint32_t off = (uint32_t)((wm * 64 + i * 16 + aRow) * SSTR + kk + aCsel) * 2;
                ldsm4(ah[i][0], ah[i][1], ah[i][2], ah[i][3], sAh + off);
            }
#pragma unroll
            for (int j2 = 0; j2 < 2; j2++) {
                uint32_t off = (uint32_t)((wn * 32 + j2 * 16 + bRow) * SSTR + kk + bCsel) * 2;
                ldsm4(bh[j2][0], bh[j2][1], bh[j2][2], bh[j2][3], sBh + off);
            }
            // hh
#pragma unroll
            for (int i = 0; i < 4; i++)
#pragma unroll
                for (int j = 0; j < 4; j++) {
                    const uint32_t* b = bh[j >> 1] + (j & 1) * 2;
                    mma16816(acc[i][j][0], acc[i][j][1], acc[i][j][2], acc[i][j][3],
                             ah[i][0], ah[i][1], ah[i][2], ah[i][3], b[0], b[1]);
                }
            // hl
#pragma unroll
            for (int j2 = 0; j2 < 2; j2++) {
                uint32_t off = (uint32_t)((wn * 32 + j2 * 16 + bRow) * SSTR + kk + bCsel) * 2;
                ldsm4(bl[j2][0], bl[j2][1], bl[j2][2], bl[j2][3], sBl + off);
            }
#pragma unroll
            for (int i = 0; i < 4; i++)
#pragma unroll
                for (int j = 0; j < 4; j++) {
                    const uint32_t* b = bl[j >> 1] + (j & 1) * 2;
                    mma16816(acc[i][j][0], acc[i][j][1], acc[i][j][2], acc[i][j][3],
                             ah[i][0], ah[i][1], ah[i][2], ah[i][3], b[0], b[1]);
                }
            // lh
#pragma unroll
            for (int i = 0; i < 4; i++) {
                uint32_t off = (uint32_t)((wm * 64 + i * 16 + aRow) * SSTR + kk + aCsel) * 2;
                ldsm4(al[i][0], al[i][1], al[i][2], al[i][3], sAl + off);
            }
#pragma unroll
            for (int i = 0; i < 4; i++)
#pragma unroll
                for (int j = 0; j < 4; j++) {
                    const uint32_t* b = bh[j >> 1] + (j & 1) * 2;
                    mma16816(acc[i][j][0], acc[i][j][1], acc[i][j][2], acc[i][j][3],
                             al[i][0], al[i][1], al[i][2], al[i][3], b[0], b[1]);
                }
        }
        __syncthreads();
    }

    const int mBase = by * 128 + wm * 64;
    const int nBase = bx * 128 + wn * 32;
    const int r0 = lane >> 2;
    const int c0 = (lane & 3) * 2;
#pragma unroll
    for (int i = 0; i < 4; i++) {
#pragma unroll
        for (int j = 0; j < 4; j++) {
            float* p0 = C + (size_t)(mBase + i * 16 + r0) * ldc + nBase + j * 8 + c0;
            *(float2*)p0                     = make_float2(acc[i][j][0], acc[i][j][1]);
            *(float2*)(p0 + (size_t)8 * ldc) = make_float2(acc[i][j][2], acc[i][j][3]);
        }
    }
}

// fixed-order split-K reduce: out = part[0..n) + part[n..2n)  (float4)
__global__ __launch_bounds__(256)
void reduce2(const float* __restrict__ part, float* __restrict__ out, int n)
{
    int i = (blockIdx.x * 256 + threadIdx.x) * 4;
    if (i >= n) return;
    float4 a = *(const float4*)(part + i);
    float4 b = *(const float4*)(part + (size_t)n + i);
    float4 r = make_float4(a.x + b.x, a.y + b.y, a.z + b.z, a.w + b.w);
    *(float4*)(out + i) = r;
}

// ---------------------------------------------------------------------------
// merged conversion kernel:
//   blocks [0, 4096):        W_in  [1024,4096] -> transpose-split [4096,1024]
//   blocks [4096, 6144):     W_out [2048,1024] -> transpose-split [1024,2048]
//   blocks [6144, 8192):     x split (row-major), float4
// ---------------------------------------------------------------------------
__device__ __forceinline__ void tsplit_body(
    const float* __restrict__ in, __nv_bfloat16* __restrict__ hiT,
    __nv_bfloat16* __restrict__ loT, int K, int N, int n0, int k0)
{
    __shared__ float t[32][33];
    int tx = threadIdx.x & 31;
    int ty = threadIdx.x >> 5;
#pragma unroll
    for (int j = 0; j < 4; j++) {
        int kk = ty + j * 8;
        t[kk][tx] = in[(size_t)(k0 + kk) * N + n0 + tx];
    }
    __syncthreads();
#pragma unroll
    for (int j = 0; j < 4; j++) {
        int a = ty + j * 8;
        float v = t[tx][a];
        __nv_bfloat16 h = __float2bfloat16(v);
        hiT[(size_t)(n0 + a) * K + k0 + tx] = h;
        loT[(size_t)(n0 + a) * K + k0 + tx] = __float2bfloat16(v - __bfloat162float(h));
    }
}

__global__ __launch_bounds__(256)
void convert_all(const float* __restrict__ x,
                 const float* __restrict__ W_in,
                 const float* __restrict__ W_out,
                 __nv_bfloat16* __restrict__ xh,  __nv_bfloat16* __restrict__ xl,
                 __nv_bfloat16* __restrict__ wih, __nv_bfloat16* __restrict__ wil,
                 __nv_bfloat16* __restrict__ woh, __nv_bfloat16* __restrict__ wol)
{
    int bid = blockIdx.x;
    if (bid < 4096) {
        // W_in: N=4096 (128 n-tiles), K=1024 (32 k-tiles)
        int n0 = (bid & 127) * 32;
        int k0 = (bid >> 7) * 32;
        tsplit_body(W_in, wih, wil, DMODEL, 4096, n0, k0);
    } else if (bid < 6144) {
        // W_out: N=1024 (32 n-tiles), K=2048 (64 k-tiles)
        int idx = bid - 4096;
        int n0 = (idx & 31) * 32;
        int k0 = (idx >> 5) * 32;
        tsplit_body(W_out, woh, wol, DINNER, DMODEL, n0, k0);
    } else {
        // x split: 2M elements, float4 per thread
        int idx = bid - 6144;                 // 0..2047
        int i = (idx * 256 + threadIdx.x) * 4;
        float4 v = *(const float4*)(x + i);
        __nv_bfloat16 h0 = __float2bfloat16(v.x);
        __nv_bfloat16 h1 = __float2bfloat16(v.y);
        __nv_bfloat16 h2 = __float2bfloat16(v.z);
        __nv_bfloat16 h3 = __float2bfloat16(v.w);
        __nv_bfloat162* ph = (__nv_bfloat162*)(xh + i);
        __nv_bfloat162* pl = (__nv_bfloat162*)(xl + i);
        ph[0] = __nv_bfloat162(h0, h1);
        ph[1] = __nv_bfloat162(h2, h3);
        pl[0] = __nv_bfloat162(__float2bfloat16(v.x - __bfloat162float(h0)),
                               __float2bfloat16(v.y - __bfloat162float(h1)));
        pl[1] = __nv_bfloat162(__float2bfloat16(v.z - __bfloat162float(h2)),
                               __float2bfloat16(v.w - __bfloat162float(h3)));
    }
}

// ---------------------------------------------------------------------------
// depthwise conv(4) + bias + silu, float4-vectorized over channels
// ---------------------------------------------------------------------------
__global__ __launch_bounds__(256)
void conv_silu_kernel(const float* __restrict__ xz,
                      const float* __restrict__ cw,
                      const float* __restrict__ cb,
                      float* __restrict__ u)
{
    int idx = blockIdx.x * blockDim.x + threadIdx.x;   // over M*DINNER/4
    if (idx >= MROWS * DINNER / 4) return;
    int d4  = (idx & (DINNER / 4 - 1)) * 4;
    int row = idx >> 9;
    int l   = row & (LL - 1);

    float4 w0 = *(const float4*)(cw + d4 * 4 + 0);
    float4 w1 = *(const float4*)(cw + d4 * 4 + 4);
    float4 w2 = *(const float4*)(cw + d4 * 4 + 8);
    float4 w3 = *(const float4*)(cw + d4 * 4 + 12);
    float4 bias = *(const float4*)(cb + d4);

    const float* base = xz + (size_t)row * (2 * DINNER) + d4;
    const int stride = 2 * DINNER;

    float4 s = bias;
    if (l >= 3) {
        float4 v = *(const float4*)(base - 3 * stride);
        s.x += v.x * w0.x; s.y += v.y * w1.x; s.z += v.z * w2.x; s.w += v.w * w3.x;
    }
    if (l >= 2) {
        float4 v = *(const float4*)(base - 2 * stride);
        s.x += v.x * w0.y; s.y += v.y * w1.y; s.z += v.z * w2.y; s.w += v.w * w3.y;
    }
    if (l >= 1) {
        float4 v = *(const float4*)(base - 1 * stride);
        s.x += v.x * w0.z; s.y += v.y * w1.z; s.z += v.z * w2.z; s.w += v.w * w3.z;
    }
    {
        float4 v = *(const float4*)(base);
        s.x += v.x * w0.w; s.y += v.y * w1.w; s.z += v.z * w2.w; s.w += v.w * w3.w;
    }
    float4 r;
    r.x = s.x / (1.f + expf(-s.x));
    r.y = s.y / (1.f + expf(-s.y));
    r.z = s.z / (1.f + expf(-s.z));
    r.w = s.w / (1.f + expf(-s.w));
    *(float4*)(u + (size_t)row * DINNER + d4) = r;
}

// ---------------------------------------------------------------------------
// xproj split-K:  part[ks] = u[:, ks*256:(ks+1)*256] @ W_xproj[ks*256.., :]
// (summed inline by the scan kernel's staging — no xprojB pass)
// ---------------------------------------------------------------------------
__global__ __launch_bounds__(256)
void xprojA(const float* __restrict__ u, const float* __restrict__ W,
            float* __restrict__ part)
{
    __shared__ float As[64 * 32];      // [r][k], stride 32
    __shared__ float Bs[96 * 36];      // [c][k], stride 36

    const int ks = blockIdx.x;
    const int mb = blockIdx.y;
    const int tid = threadIdx.x;
    const int rg = tid >> 4;
    const int cg = tid & 15;

    float acc[4][6];
#pragma unroll
    for (int r = 0; r < 4; r++)
#pragma unroll
        for (int j = 0; j < 6; j++) acc[r][j] = 0.f;

    for (int kc = 0; kc < 8; kc++) {
        const int kbase = ks * 256 + kc * 32;
#pragma unroll
        for (int i = tid; i < 64 * 32; i += 256) {
            int r = i >> 5, k = i & 31;
            As[r * 32 + k] = u[(size_t)(mb * 64 + r) * DINNER + kbase + k];
        }
#pragma unroll
        for (int i = tid; i < 96 * 32; i += 256) {
            int c = i % 96, k = i / 96;
            Bs[c * 36 + k] = W[(size_t)(kbase + k) * XPROJ_N + c];
        }
        __syncthreads();
#pragma unroll
        for (int kq = 0; kq < 8; kq++) {
            float4 a[4], b[6];
#pragma unroll
            for (int r = 0; r < 4; r++)
                a[r] = *(const float4*)&As[(rg * 4 + r) * 32 + kq * 4];
#pragma unroll
            for (int j = 0; j < 6; j++)
                b[j] = *(const float4*)&Bs[(j * 16 + cg) * 36 + kq * 4];
#pragma unroll
            for (int r = 0; r < 4; r++)
#pragma unroll
                for (int j = 0; j < 6; j++)
                    acc[r][j] += a[r].x * b[j].x + a[r].y * b[j].y
                               + a[r].z * b[j].z + a[r].w * b[j].w;
        }
        __syncthreads();
    }
#pragma unroll
    for (int r = 0; r < 4; r++)
#pragma unroll
        for (int j = 0; j < 6; j++)
            part[((size_t)ks * MROWS + mb * 64 + rg * 4 + r) * XPROJ_N + j * 16 + cg]
                = acc[r][j];
}

// ---------------------------------------------------------------------------
// selective scan:
//   - staging sums the 8 xproj split-K partials inline (xprojB fused)
//   - fused delta GEMM (dt_lr @ W_dt + b_dt -> softplus), float4 vectorized
//   - serial step: 2 LDS.64 + MUFU + FFMA chain (1 FFMA critical path)
//   - parallel reduce over n emits y -> bf16 hi/lo
// Chunk = 32 timesteps.  Dynamic smem, 60288 B.
// ---------------------------------------------------------------------------
#define SCT 32
#define OFF_WT    0                       // [16][68]  W_dt^T slice      1088
#define OFF_DT    1088                    // [32][68]  dt_lr rows        2176
#define OFF_BC    3264                    // [32][16] float2 (B,C)       1024
#define OFF_DU    4288                    // [32][16] float2 (del,del*u) 1024
#define OFF_U     5312                    // [32][16]                    512
#define OFF_Z     5824                    // [32][16]                    512
#define OFF_BD    6336                    // [16]
#define OFF_DSK   6352                    // [16]
#define OFF_P     6368                    // [32][16][17]                8704
#define SCAN_SMEM ((6368 + 8704) * 4)     // 60288 bytes

__global__ __launch_bounds__(256)
void scan_kernel(const float* __restrict__ u,
                 const float* __restrict__ xz,
                 const float* __restrict__ xpart,  // [8][MROWS][96]
                 const float* __restrict__ W_dt,   // [64, 2048]
                 const float* __restrict__ b_dt,   // [2048]
                 const float* __restrict__ A_log,
                 const float* __restrict__ Dskip,
                 __nv_bfloat16* __restrict__ yh,
                 __nv_bfloat16* __restrict__ yl)
{
    extern __shared__ float sm[];
    float* sWT  = sm + OFF_WT;    // [c][k] stride 68
    float* sDT  = sm + OFF_DT;    // [r][k] stride 68
    float* sBC  = sm + OFF_BC;    // float2 [t][n]
    float* sDU  = sm + OFF_DU;    // float2 [t][d]
    float* sU   = sm + OFF_U;
    float* sZ   = sm + OFF_Z;
    float* sbd  = sm + OFF_BD;
    float* sdsk = sm + OFF_DSK;
    float* sP   = sm + OFF_P;

    const int tid = threadIdx.x;
    const int tn = tid & 15;
    const int td = tid >> 4;
    const int dbase = blockIdx.x * 16;
    const int b = blockIdx.y;

    for (int i = tid; i < 1024; i += 256) {
        int k = i >> 4, c = i & 15;
        sWT[c * 68 + k] = W_dt[(size_t)k * DINNER + dbase + c];
    }
    if (tid < 16) {
        sbd[tid]  = b_dt[dbase + tid];
        sdsk[tid] = Dskip[dbase + tid];
    }
    const float Aq = -expf(A_log[(dbase + td) * DSTATE + tn]);
    __syncthreads();

    float h = 0.f;

    for (int t0 = 0; t0 < LL; t0 += SCT) {
        // ---- stage: xdbl rows reconstructed from 8 partials (xprojB fused)
#pragma unroll
        for (int i = tid; i < SCT * 24; i += 256) {    // 3 iters
            int r = i / 24, q = i - r * 24;
            size_t base = (size_t)(b * LL + t0 + r) * XPROJ_N + q * 4;
            float4 v = make_float4(0.f, 0.f, 0.f, 0.f);
#pragma unroll
            for (int ks = 0; ks < KSPLITS; ks++) {
                float4 t4 = *(const float4*)(xpart + (size_t)ks * MROWS * XPROJ_N + base);
                v.x += t4.x; v.y += t4.y; v.z += t4.z; v.w += t4.w;
            }
            if (q < 16) {
                *(float4*)(sDT + r * 68 + q * 4) = v;
            } else if (q < 20) {
                int nb = (q - 16) * 4;
                sBC[(r * 16 + nb + 0) * 2] = v.x;
                sBC[(r * 16 + nb + 1) * 2] = v.y;
                sBC[(r * 16 + nb + 2) * 2] = v.z;
                sBC[(r * 16 + nb + 3) * 2] = v.w;
            } else {
                int nb = (q - 20) * 4;
                sBC[(r * 16 + nb + 0) * 2 + 1] = v.x;
                sBC[(r * 16 + nb + 1) * 2 + 1] = v.y;
                sBC[(r * 16 + nb + 2) * 2 + 1] = v.z;
                sBC[(r * 16 + nb + 3) * 2 + 1] = v.w;
            }
        }
#pragma unroll
        for (int i = tid; i < SCT * 16; i += 256) {    // 2 iters
            int r = i >> 4, c = i & 15;
            int row = b * LL + t0 + r;
            sU[i] = u[(size_t)row * DINNER + dbase + c];
            sZ[i] = xz[(size_t)row * (2 * DINNER) + DINNER + dbase + c];
        }
        __syncthreads();

        // ---- delta pass (vectorized): rows r0 and r0+16, col c ----
        {
            const int c  = tid & 15;
            const int r0 = tid >> 4;
            float s0 = sbd[c], s1 = s0;
#pragma unroll
            for (int kb = 0; kb < 16; kb++) {
                float4 w  = *(const float4*)(sWT + c * 68 + kb * 4);
                float4 a0 = *(const float4*)(sDT + r0 * 68 + kb * 4);
                float4 a1 = *(const float4*)(sDT + (r0 + 16) * 68 + kb * 4);
                s0 += a0.x * w.x + a0.y * w.y + a0.z * w.z + a0.w * w.w;
                s1 += a1.x * w.x + a1.y * w.y + a1.z * w.z + a1.w * w.w;
            }
            float d0 = (s0 > 20.f) ? s0 : log1pf(expf(s0));
            float d1 = (s1 > 20.f) ? s1 : log1pf(expf(s1));
            float du0 = d0 * sU[r0 * 16 + c];
            float du1 = d1 * sU[(r0 + 16) * 16 + c];
            sDU[(r0 * 16 + c) * 2]            = d0;
            sDU[(r0 * 16 + c) * 2 + 1]        = du0;
            sDU[((r0 + 16) * 16 + c) * 2]     = d1;
            sDU[((r0 + 16) * 16 + c) * 2 + 1] = du1;
        }
        __syncthreads();

        // ---- serial recurrence ----
#pragma unroll 16
        for (int tt = 0; tt < SCT; tt++) {
            float2 du = *(const float2*)(sDU + (tt * 16 + td) * 2);
            float2 bc = *(const float2*)(sBC + (tt * 16 + tn) * 2);
            float dA = __expf(du.x * Aq);
            h = dA * h + du.y * bc.x;
            sP[(tt * 16 + td) * 17 + tn] = h * bc.y;
        }
        __syncthreads();

        // ---- parallel reduce over n + gate + bf16 split output ----
#pragma unroll
        for (int v = 0; v < 2; v++) {
            int o = tid + v * 256;
            int tt = o >> 4, c = o & 15;
            const float* p = sP + (tt * 16 + c) * 17;
            float s = 0.f;
#pragma unroll
            for (int n = 0; n < 16; n++) s += p[n];
            float uu = sU[tt * 16 + c];
            float zz = sZ[tt * 16 + c];
            float yv = s + sdsk[c] * uu;
            yv *= zz / (1.f + expf(-zz));
            int row = b * LL + t0 + tt;
            __nv_bfloat16 hb = __float2bfloat16(yv);
            yh[(size_t)row * DINNER + dbase + c] = hb;
            yl[(size_t)row * DINNER + dbase + c] =
                __float2bfloat16(yv - __bfloat162float(hb));
        }
        __syncthreads();
    }
}

// ---------------------------------------------------------------------------
extern "C" void kernel_launch(void* const* d_in, const int* in_sizes, int n_in,
                              void* d_out, int out_size)
{
    const float* x       = (const float*)d_in[0];  // [2,1024,1024]
    const float* W_in    = (const float*)d_in[1];  // [1024, 4096]
    const float* conv_w  = (const float*)d_in[2];  // [2048, 1, 4]
    const float* conv_b  = (const float*)d_in[3];  // [2048]
    const float* W_xproj = (const float*)d_in[4];  // [2048, 96]
    const float* W_dt    = (const float*)d_in[5];  // [64, 2048]
    const float* b_dt    = (const float*)d_in[6];  // [2048]
    const float* A_log   = (const float*)d_in[7];  // [2048, 16]
    const float* D_skip  = (const float*)d_in[8];  // [2048]
    const float* W_out   = (const float*)d_in[9];  // [2048, 1024]
    float* out = (float*)d_out;                    // [2,1024,1024]

    float* xz;    cudaGetSymbolAddress((void**)&xz,    g_xz);
    float* u;     cudaGetSymbolAddress((void**)&u,     g_u);
    float* xpart; cudaGetSymbolAddress((void**)&xpart, g_xpart);
    float* part;  cudaGetSymbolAddress((void**)&part,  g_part);

    __nv_bfloat16 *xh, *xl, *winTh, *winTl, *yh, *yl, *woutTh, *woutTl;
    cudaGetSymbolAddress((void**)&xh,     g_xh);
    cudaGetSymbolAddress((void**)&xl,     g_xl);
    cudaGetSymbolAddress((void**)&winTh,  g_winT_h);
    cudaGetSymbolAddress((void**)&winTl,  g_winT_l);
    cudaGetSymbolAddress((void**)&yh,     g_yh);
    cudaGetSymbolAddress((void**)&yl,     g_yl);
    cudaGetSymbolAddress((void**)&woutTh, g_woutT_h);
    cudaGetSymbolAddress((void**)&woutTl, g_woutT_l);

    cudaFuncSetAttribute(gemm_mma, cudaFuncAttributeMaxDynamicSharedMemorySize, GM_SMEM);
    cudaFuncSetAttribute(scan_kernel, cudaFuncAttributeMaxDynamicSharedMemorySize, SCAN_SMEM);

    // 0) all operand conversions in one launch
    convert_all<<<8192, 256>>>(x, W_in, W_out, xh, xl, winTh, winTl, woutTh, woutTl);

    // 1) xz = x @ W_in        [2048,1024] @ [1024,4096]   (tensor cores)
    gemm_mma<<<dim3(4096 / 128, MROWS / 128, 1), 256, GM_SMEM>>>(
        xh, xl, winTh, winTl, xz, DMODEL, 4096, DMODEL, 0);

    // 2) u = silu(conv(xz[:, :2048]) + conv_b)
    conv_silu_kernel<<<(MROWS * DINNER / 4 + 255) / 256, 256>>>(xz, conv_w, conv_b, u);

    // 3) xproj partials (summed inside scan)
    xprojA<<<dim3(KSPLITS, MROWS / 64), 256>>>(u, W_xproj, xpart);

    // 4+5) fused xprojB + delta + selective scan -> yh/yl (bf16 split)
    scan_kernel<<<dim3(DINNER / 16, BB), 256, SCAN_SMEM>>>(
        u, xz, xpart, W_dt, b_dt, A_log, D_skip, yh, yl);

    // 6) out = y @ W_out   [2048,2048]@[2048,1024], 2-way split-K + reduce
    gemm_mma<<<dim3(1024 / 128, MROWS / 128, 2), 256, GM_SMEM>>>(
        yh, yl, woutTh, woutTl, part, DINNER, 1024, 1024,
        (size_t)MROWS * DMODEL);
    reduce2<<<(MROWS * DMODEL / 4 + 255) / 256, 256>>>(part, out, MROWS * DMODEL);
}

// round 11
// speedup vs baseline: 1.0932x; 1.0932x over previous
#include <cuda_runtime.h>
#include <cuda_bf16.h>
#include <math.h>
#include <cstdint>

// ---------------------------------------------------------------------------
// TemporalMamba: B=2, L=1024, D_MODEL=1024, D_INNER=2048, D_STATE=16,
// D_CONV=4, DT_RANK=64.
// Tensor cores via mma.sync.m16n8k16 bf16x3 split (toolchain is compute_100
// base: tcgen05 unavailable).
// ---------------------------------------------------------------------------

#define BB       2
#define LL       1024
#define DMODEL   1024
#define DINNER   2048
#define DSTATE   16
#define DTRANK   64
#define MROWS    (BB * LL)                  // 2048
#define XPROJ_N  (DTRANK + 2 * DSTATE)      // 96
#define KSPLITS  16

// ------------------------- scratch (device globals) ------------------------
__device__ float g_xz[MROWS * 2 * DINNER];      // [M, 4096]
__device__ float g_u[MROWS * DINNER];           // [M, 2048]
__device__ float g_xdbl[MROWS * XPROJ_N];       // [M, 96]
__device__ float g_xpart[KSPLITS * MROWS * XPROJ_N];  // xproj split-K partials
__device__ float g_part[2 * MROWS * DMODEL];    // GEMM4 split-K partials

// bf16 split operands
__device__ __nv_bfloat16 g_xh[MROWS * DMODEL];
__device__ __nv_bfloat16 g_xl[MROWS * DMODEL];
__device__ __nv_bfloat16 g_winT_h[4096 * DMODEL];
__device__ __nv_bfloat16 g_winT_l[4096 * DMODEL];
__device__ __nv_bfloat16 g_yh[MROWS * DINNER];
__device__ __nv_bfloat16 g_yl[MROWS * DINNER];
__device__ __nv_bfloat16 g_woutT_h[DMODEL * DINNER];
__device__ __nv_bfloat16 g_woutT_l[DMODEL * DINNER];

// ---------------------------------------------------------------------------
// mma.sync / ldmatrix / cp.async helpers
// ---------------------------------------------------------------------------
__device__ __forceinline__ uint32_t smem_u32(const void* p) {
    uint32_t a;
    asm("{ .reg .u64 t; cvta.to.shared.u64 t, %1; cvt.u32.u64 %0, t; }" : "=r"(a) : "l"(p));
    return a;
}
__device__ __forceinline__ void cpa16(uint32_t s, const void* g) {
    asm volatile("cp.async.cg.shared.global [%0], [%1], 16;" :: "r"(s), "l"(g));
}
__device__ __forceinline__ void ldsm4(uint32_t& r0, uint32_t& r1, uint32_t& r2, uint32_t& r3,
                                      uint32_t addr) {
    asm volatile("ldmatrix.sync.aligned.m8n8.x4.shared.b16 {%0,%1,%2,%3}, [%4];"
                 : "=r"(r0), "=r"(r1), "=r"(r2), "=r"(r3) : "r"(addr));
}
__device__ __forceinline__ void mma16816(float& c0, float& c1, float& c2, float& c3,
                                         uint32_t a0, uint32_t a1, uint32_t a2, uint32_t a3,
                                         uint32_t b0, uint32_t b1) {
    asm volatile(
        "mma.sync.aligned.m16n8k16.row.col.f32.bf16.bf16.f32 "
        "{%0,%1,%2,%3}, {%4,%5,%6,%7}, {%8,%9}, {%0,%1,%2,%3};"
        : "+f"(c0), "+f"(c1), "+f"(c2), "+f"(c3)
        : "r"(a0), "r"(a1), "r"(a2), "r"(a3), "r"(b0), "r"(b1));
}

// ---------------------------------------------------------------------------
// bf16x3 split tensor-core GEMM:  C[M,N] = (Ah+Al)[M,K] @ (Bh+Bl)^T
//   A row-major [M][K], B as Bt[N][K] (K-major).  CTA: 256 thr = 8 warps
//   (2 M x 4 N), tile 128x128, warp tile 64x32, BK=32, cp.async double
//   buffer, 2 CTAs/SM.  Terms: AhBh + AhBl + AlBh, fp32 accumulate.
//   gridDim.z splits K deterministically; z writes C + z*partStride.
// ---------------------------------------------------------------------------
#define SSTR     40                                  // smem row stride (bf16)
#define TILE_B   (128 * SSTR * 2)                    // 10240 B per tile
#define STAGE_B  (4 * TILE_B)                        // Ah, Al, Bh, Bl
#define GM_SMEM  (2 * STAGE_B)                       // 81920 B

__device__ __forceinline__ void load_stage_tile(
    const __nv_bfloat16* __restrict__ G, int rowBase, int k0, int K,
    uint32_t sdst, int tid)
{
#pragma unroll
    for (int i = 0; i < 2; i++) {
        int idx = tid + i * 256;            // 0..511
        int r = idx >> 2;                   // row 0..127
        int q = idx & 3;                    // 16B chunk in 64B row
        const void* g = G + (size_t)(rowBase + r) * K + k0 + q * 8;
        cpa16(sdst + (uint32_t)(r * SSTR + q * 8) * 2, g);
    }
}

__global__ __launch_bounds__(256, 2)
void gemm_mma(const __nv_bfloat16* __restrict__ Ah, const __nv_bfloat16* __restrict__ Al,
              const __nv_bfloat16* __restrict__ Bh, const __nv_bfloat16* __restrict__ Bl,
              float* __restrict__ C, int Kfull, int ldc, int kdepth,
              size_t partStride)
{
    extern __shared__ __align__(16) char dsm[];
    const uint32_t sbase = smem_u32(dsm);

    const int tid  = threadIdx.x;
    const int wid  = tid >> 5;
    const int lane = tid & 31;
    const int wm   = wid >> 2;              // 0..1  (M)
    const int wn   = wid & 3;               // 0..3  (N)
    const int bx   = blockIdx.x, by = blockIdx.y;
    const int kbase = blockIdx.z * kdepth;
    C += (size_t)blockIdx.z * partStride;

    const int aRow  = lane & 15;
    const int aCsel = (lane >> 4) * 8;
    const int bRow  = (lane & 7) + ((lane >> 4) << 3);
    const int bCsel = ((lane >> 3) & 1) * 8;

    float acc[4][4][4];
#pragma unroll
    for (int i = 0; i < 4; i++)
#pragma unroll
        for (int j = 0; j < 4; j++)
#pragma unroll
            for (int v = 0; v < 4; v++) acc[i][j][v] = 0.f;

    const int NC = kdepth >> 5;

    load_stage_tile(Ah, by * 128, kbase, Kfull, sbase + 0 * TILE_B, tid);
    load_stage_tile(Al, by * 128, kbase, Kfull, sbase + 1 * TILE_B, tid);
    load_stage_tile(Bh, bx * 128, kbase, Kfull, sbase + 2 * TILE_B, tid);
    load_stage_tile(Bl, bx * 128, kbase, Kfull, sbase + 3 * TILE_B, tid);
    asm volatile("cp.async.commit_group;");

    for (int c = 0; c < NC; c++) {
        if (c + 1 < NC) {
            const uint32_t sd = sbase + ((c + 1) & 1) * STAGE_B;
            const int k0 = kbase + ((c + 1) << 5);
            load_stage_tile(Ah, by * 128, k0, Kfull, sd + 0 * TILE_B, tid);
            load_stage_tile(Al, by * 128, k0, Kfull, sd + 1 * TILE_B, tid);
            load_stage_tile(Bh, bx * 128, k0, Kfull, sd + 2 * TILE_B, tid);
            load_stage_tile(Bl, bx * 128, k0, Kfull, sd + 3 * TILE_B, tid);
            asm volatile("cp.async.commit_group;");
            asm volatile("cp.async.wait_group 1;");
        } else {
            asm volatile("cp.async.wait_group 0;");
        }
        __syncthreads();

        const uint32_t st = sbase + (c & 1) * STAGE_B;
        const uint32_t sAh = st + 0 * TILE_B;
        const uint32_t sAl = st + 1 * TILE_B;
        const uint32_t sBh = st + 2 * TILE_B;
        const uint32_t sBl = st + 3 * TILE_B;

#pragma unroll
        for (int kk = 0; kk < 32; kk += 16) {
            uint32_t ah[4][4], al[4][4], bh[2][4], bl[2][4];
#pragma unroll
            for (int i = 0; i < 4; i++) {
                uint32_t off = (uint32_t)((wm * 64 + i * 16 + aRow) * SSTR + kk + aCsel) * 2;
                ldsm4(ah[i][0], ah[i][1], ah[i][2], ah[i][3], sAh + off);
            }
#pragma unroll
            for (int j2 = 0; j2 < 2; j2++) {
                uint32_t off = (uint32_t)((wn * 32 + j2 * 16 + bRow) * SSTR + kk + bCsel) * 2;
                ldsm4(bh[j2][0], bh[j2][1], bh[j2][2], bh[j2][3], sBh + off);
            }
            // hh
#pragma unroll
            for (int i = 0; i < 4; i++)
#pragma unroll
                for (int j = 0; j < 4; j++) {
                    const uint32_t* b = bh[j >> 1] + (j & 1) * 2;
                    mma16816(acc[i][j][0], acc[i][j][1], acc[i][j][2], acc[i][j][3],
                             ah[i][0], ah[i][1], ah[i][2], ah[i][3], b[0], b[1]);
                }
            // hl
#pragma unroll
            for (int j2 = 0; j2 < 2; j2++) {
                uint32_t off = (uint32_t)((wn * 32 + j2 * 16 + bRow) * SSTR + kk + bCsel) * 2;
                ldsm4(bl[j2][0], bl[j2][1], bl[j2][2], bl[j2][3], sBl + off);
            }
#pragma unroll
            for (int i = 0; i < 4; i++)
#pragma unroll
                for (int j = 0; j < 4; j++) {
                    const uint32_t* b = bl[j >> 1] + (j & 1) * 2;
                    mma16816(acc[i][j][0], acc[i][j][1], acc[i][j][2], acc[i][j][3],
                             ah[i][0], ah[i][1], ah[i][2], ah[i][3], b[0], b[1]);
                }
            // lh
#pragma unroll
            for (int i = 0; i < 4; i++) {
                uint32_t off = (uint32_t)((wm * 64 + i * 16 + aRow) * SSTR + kk + aCsel) * 2;
                ldsm4(al[i][0], al[i][1], al[i][2], al[i][3], sAl + off);
            }
#pragma unroll
            for (int i = 0; i < 4; i++)
#pragma unroll
                for (int j = 0; j < 4; j++) {
                    const uint32_t* b = bh[j >> 1] + (j & 1) * 2;
                    mma16816(acc[i][j][0], acc[i][j][1], acc[i][j][2], acc[i][j][3],
                             al[i][0], al[i][1], al[i][2], al[i][3], b[0], b[1]);
                }
        }
        __syncthreads();
    }

    const int mBase = by * 128 + wm * 64;
    const int nBase = bx * 128 + wn * 32;
    const int r0 = lane >> 2;
    const int c0 = (lane & 3) * 2;
#pragma unroll
    for (int i = 0; i < 4; i++) {
#pragma unroll
        for (int j = 0; j < 4; j++) {
            float* p0 = C + (size_t)(mBase + i * 16 + r0) * ldc + nBase + j * 8 + c0;
            *(float2*)p0                     = make_float2(acc[i][j][0], acc[i][j][1]);
            *(float2*)(p0 + (size_t)8 * ldc) = make_float2(acc[i][j][2], acc[i][j][3]);
        }
    }
}

// fixed-order split-K reduce: out = part[0..n) + part[n..2n)  (float4)
__global__ __launch_bounds__(256)
void reduce2(const float* __restrict__ part, float* __restrict__ out, int n)
{
    int i = (blockIdx.x * 256 + threadIdx.x) * 4;
    if (i >= n) return;
    float4 a = *(const float4*)(part + i);
    float4 b = *(const float4*)(part + (size_t)n + i);
    float4 r = make_float4(a.x + b.x, a.y + b.y, a.z + b.z, a.w + b.w);
    *(float4*)(out + i) = r;
}

// ---------------------------------------------------------------------------
// fp32 -> bf16 hi/lo split (row-major)
// ---------------------------------------------------------------------------
__global__ __launch_bounds__(256)
void split_fp32_bf16(const float* __restrict__ in, __nv_bfloat16* __restrict__ hi,
                     __nv_bfloat16* __restrict__ lo, int n)
{
    int i = blockIdx.x * 256 + threadIdx.x;
    if (i >= n) return;
    float a = in[i];
    __nv_bfloat16 h = __float2bfloat16(a);
    hi[i] = h;
    lo[i] = __float2bfloat16(a - __bfloat162float(h));
}

// transpose + split:  in[K][N] fp32  ->  hiT/loT [N][K] bf16
__global__ __launch_bounds__(256)
void tsplit_fp32_bf16(const float* __restrict__ in,
                      __nv_bfloat16* __restrict__ hiT, __nv_bfloat16* __restrict__ loT,
                      int K, int N)
{
    __shared__ float t[32][33];
    int tx = threadIdx.x & 31;
    int ty = threadIdx.x >> 5;
    int n0 = blockIdx.x * 32;
    int k0 = blockIdx.y * 32;
#pragma unroll
    for (int j = 0; j < 4; j++) {
        int kk = ty + j * 8;
        t[kk][tx] = in[(size_t)(k0 + kk) * N + n0 + tx];
    }
    __syncthreads();
#pragma unroll
    for (int j = 0; j < 4; j++) {
        int a = ty + j * 8;
        float v = t[tx][a];
        __nv_bfloat16 h = __float2bfloat16(v);
        hiT[(size_t)(n0 + a) * K + k0 + tx] = h;
        loT[(size_t)(n0 + a) * K + k0 + tx] = __float2bfloat16(v - __bfloat162float(h));
    }
}

// ---------------------------------------------------------------------------
// depthwise conv(4) + bias + silu, float4-vectorized over channels
// ---------------------------------------------------------------------------
__global__ __launch_bounds__(256)
void conv_silu_kernel(const float* __restrict__ xz,
                      const float* __restrict__ cw,
                      const float* __restrict__ cb,
                      float* __restrict__ u)
{
    int idx = blockIdx.x * blockDim.x + threadIdx.x;   // over M*DINNER/4
    if (idx >= MROWS * DINNER / 4) return;
    int d4  = (idx & (DINNER / 4 - 1)) * 4;
    int row = idx >> 9;
    int l   = row & (LL - 1);

    float4 w0 = *(const float4*)(cw + d4 * 4 + 0);
    float4 w1 = *(const float4*)(cw + d4 * 4 + 4);
    float4 w2 = *(const float4*)(cw + d4 * 4 + 8);
    float4 w3 = *(const float4*)(cw + d4 * 4 + 12);
    float4 bias = *(const float4*)(cb + d4);

    const float* base = xz + (size_t)row * (2 * DINNER) + d4;
    const int stride = 2 * DINNER;

    float4 s = bias;
    if (l >= 3) {
        float4 v = *(const float4*)(base - 3 * stride);
        s.x += v.x * w0.x; s.y += v.y * w1.x; s.z += v.z * w2.x; s.w += v.w * w3.x;
    }
    if (l >= 2) {
        float4 v = *(const float4*)(base - 2 * stride);
        s.x += v.x * w0.y; s.y += v.y * w1.y; s.z += v.z * w2.y; s.w += v.w * w3.y;
    }
    if (l >= 1) {
        float4 v = *(const float4*)(base - 1 * stride);
        s.x += v.x * w0.z; s.y += v.y * w1.z; s.z += v.z * w2.z; s.w += v.w * w3.z;
    }
    {
        float4 v = *(const float4*)(base);
        s.x += v.x * w0.w; s.y += v.y * w1.w; s.z += v.z * w2.w; s.w += v.w * w3.w;
    }
    float4 r;
    r.x = s.x / (1.f + expf(-s.x));
    r.y = s.y / (1.f + expf(-s.y));
    r.z = s.z / (1.f + expf(-s.z));
    r.w = s.w / (1.f + expf(-s.w));
    *(float4*)(u + (size_t)row * DINNER + d4) = r;
}

// ---------------------------------------------------------------------------
// xproj split-K (16-way):  part[ks] = u[:, ks*128:(ks+1)*128] @ W_xproj[...]
// grid (16, 32): 512 CTAs (vs 256 at 8-way; fixes the 1.7-wave tail).
// ---------------------------------------------------------------------------
#define XKD (DINNER / KSPLITS)             // 128 K per split
__global__ __launch_bounds__(256)
void xprojA(const float* __restrict__ u, const float* __restrict__ W,
            float* __restrict__ part)
{
    __shared__ float As[64 * 32];      // [r][k], stride 32
    __shared__ float Bs[96 * 36];      // [c][k], stride 36

    const int ks = blockIdx.x;
    const int mb = blockIdx.y;
    const int tid = threadIdx.x;
    const int rg = tid >> 4;
    const int cg = tid & 15;

    float acc[4][6];
#pragma unroll
    for (int r = 0; r < 4; r++)
#pragma unroll
        for (int j = 0; j < 6; j++) acc[r][j] = 0.f;

    for (int kc = 0; kc < XKD / 32; kc++) {
        const int kbase = ks * XKD + kc * 32;
#pragma unroll
        for (int i = tid; i < 64 * 32; i += 256) {
            int r = i >> 5, k = i & 31;
            As[r * 32 + k] = u[(size_t)(mb * 64 + r) * DINNER + kbase + k];
        }
#pragma unroll
        for (int i = tid; i < 96 * 32; i += 256) {
            int c = i % 96, k = i / 96;
            Bs[c * 36 + k] = W[(size_t)(kbase + k) * XPROJ_N + c];
        }
        __syncthreads();
#pragma unroll
        for (int kq = 0; kq < 8; kq++) {
            float4 a[4], b[6];
#pragma unroll
            for (int r = 0; r < 4; r++)
                a[r] = *(const float4*)&As[(rg * 4 + r) * 32 + kq * 4];
#pragma unroll
            for (int j = 0; j < 6; j++)
                b[j] = *(const float4*)&Bs[(j * 16 + cg) * 36 + kq * 4];
#pragma unroll
            for (int r = 0; r < 4; r++)
#pragma unroll
                for (int j = 0; j < 6; j++)
                    acc[r][j] += a[r].x * b[j].x + a[r].y * b[j].y
                               + a[r].z * b[j].z + a[r].w * b[j].w;
        }
        __syncthreads();
    }
#pragma unroll
    for (int r = 0; r < 4; r++)
#pragma unroll
        for (int j = 0; j < 6; j++)
            part[((size_t)ks * MROWS + mb * 64 + rg * 4 + r) * XPROJ_N + j * 16 + cg]
                = acc[r][j];
}

__global__ __launch_bounds__(256)
void xprojB(const float* __restrict__ part, float* __restrict__ xdbl)
{
    int idx = blockIdx.x * 256 + threadIdx.x;
    if (idx >= MROWS * XPROJ_N) return;
    float s = 0.f;
#pragma unroll
    for (int ks = 0; ks < KSPLITS; ks++)
        s += part[(size_t)ks * MROWS * XPROJ_N + idx];
    xdbl[idx] = s;
}

// ---------------------------------------------------------------------------
// selective scan (R8 structure — measured best):
//   - fused delta GEMM (dt_lr @ W_dt + b_dt -> softplus)
//   - serial phase: only h = dA*h + dBu on the critical path; p = h*c -> smem
//   - parallel reduce over n emits y -> bf16 hi/lo
// Chunk = 32 timesteps.  Dynamic smem 57472 B.
// ---------------------------------------------------------------------------
#define SCT 32
#define OFF_W     0                       // [64][16]     1024
#define OFF_BD    1024                    // [16]
#define OFF_DSK   1040                    // [16]
#define OFF_DT    1056                    // [32][64]     2048
#define OFF_DEL   3104                    // [32][16]     512
#define OFF_U     3616                    // [32][16]     512
#define OFF_Z     4128                    // [32][16]     512
#define OFF_B     4640                    // [32][16]     512
#define OFF_C     5152                    // [32][16]     512
#define OFF_P     5664                    // [32][16][17] 8704
#define SCAN_SMEM ((5664 + 8704) * 4)     // 57472 bytes

__global__ __launch_bounds__(256)
void scan_kernel(const float* __restrict__ u,
                 const float* __restrict__ xz,
                 const float* __restrict__ xdbl,
                 const float* __restrict__ W_dt,   // [64, 2048]
                 const float* __restrict__ b_dt,   // [2048]
                 const float* __restrict__ A_log,
                 const float* __restrict__ Dskip,
                 __nv_bfloat16* __restrict__ yh,
                 __nv_bfloat16* __restrict__ yl)
{
    extern __shared__ float sm[];
    float* sW   = sm + OFF_W;
    float* sbd  = sm + OFF_BD;
    float* sdsk = sm + OFF_DSK;
    float* sDT  = sm + OFF_DT;
    float* sDel = sm + OFF_DEL;
    float* sU   = sm + OFF_U;
    float* sZ   = sm + OFF_Z;
    float* sB   = sm + OFF_B;
    float* sC   = sm + OFF_C;
    float* sP   = sm + OFF_P;

    const int tid = threadIdx.x;
    const int tn = tid & 15;
    const int td = tid >> 4;
    const int dbase = blockIdx.x * 16;
    const int b = blockIdx.y;

    for (int i = tid; i < 64 * 16; i += 256) {
        int r = i >> 4, c = i & 15;
        sW[i] = W_dt[(size_t)r * DINNER + dbase + c];
    }
    if (tid < 16) {
        sbd[tid]  = b_dt[dbase + tid];
        sdsk[tid] = Dskip[dbase + tid];
    }
    const float Aq = -expf(A_log[(dbase + td) * DSTATE + tn]);
    __syncthreads();

    float h = 0.f;

    for (int t0 = 0; t0 < LL; t0 += SCT) {
        // ---- stage ----
#pragma unroll
        for (int i = tid; i < SCT * 16; i += 256) {     // 2 iters
            int r = i >> 4, c = i & 15;
            int row = b * LL + t0 + r;
            sU[i] = u[(size_t)row * DINNER + dbase + c];
            sZ[i] = xz[(size_t)row * (2 * DINNER) + DINNER + dbase + c];
            sB[i] = xdbl[(size_t)row * XPROJ_N + DTRANK + c];
            sC[i] = xdbl[(size_t)row * XPROJ_N + DTRANK + DSTATE + c];
        }
#pragma unroll
        for (int i = tid; i < SCT * 64; i += 256) {     // 8 iters
            int r = i >> 6, k = i & 63;
            sDT[i] = xdbl[(size_t)(b * LL + t0 + r) * XPROJ_N + k];
        }
        __syncthreads();

        // ---- fused delta (2 outputs/thread; rows r0 and r0+16) ----
        {
            const int c = tid & 15;
            const int r0 = tid >> 4;
            float s0 = sbd[c], s1 = sbd[c];
#pragma unroll 8
            for (int k = 0; k < 64; k++) {
                float w = sW[k * 16 + c];
                s0 += sDT[r0 * 64 + k] * w;
                s1 += sDT[(r0 + 16) * 64 + k] * w;
            }
            sDel[r0 * 16 + c]        = (s0 > 20.f) ? s0 : log1pf(expf(s0));
            sDel[(r0 + 16) * 16 + c] = (s1 > 20.f) ? s1 : log1pf(expf(s1));
        }
        __syncthreads();

        // ---- serial recurrence: critical path = 1 FFMA/step ----
#pragma unroll 8
        for (int tt = 0; tt < SCT; tt++) {
            float dlt = sDel[tt * 16 + td];
            float uu  = sU[tt * 16 + td];
            float bb  = sB[tt * 16 + tn];
            float cc  = sC[tt * 16 + tn];
            float dA  = __expf(dlt * Aq);
            h = dA * h + (dlt * uu) * bb;
            sP[(tt * 16 + td) * 17 + tn] = h * cc;
        }
        __syncthreads();

        // ---- parallel reduce over n + gate + bf16 split output ----
#pragma unroll
        for (int v = 0; v < 2; v++) {
            int o = tid + v * 256;
            int tt = o >> 4, c = o & 15;
            const float* p = sP + (tt * 16 + c) * 17;
            float s = 0.f;
#pragma unroll
            for (int n = 0; n < 16; n++) s += p[n];
            float uu = sU[tt * 16 + c];
            float zz = sZ[tt * 16 + c];
            float yv = s + sdsk[c] * uu;
            yv *= zz / (1.f + expf(-zz));
            int row = b * LL + t0 + tt;
            __nv_bfloat16 hb = __float2bfloat16(yv);
            yh[(size_t)row * DINNER + dbase + c] = hb;
            yl[(size_t)row * DINNER + dbase + c] =
                __float2bfloat16(yv - __bfloat162float(hb));
        }
        __syncthreads();
    }
}

// ---------------------------------------------------------------------------
extern "C" void kernel_launch(void* const* d_in, const int* in_sizes, int n_in,
                              void* d_out, int out_size)
{
    const float* x       = (const float*)d_in[0];  // [2,1024,1024]
    const float* W_in    = (const float*)d_in[1];  // [1024, 4096]
    const float* conv_w  = (const float*)d_in[2];  // [2048, 1, 4]
    const float* conv_b  = (const float*)d_in[3];  // [2048]
    const float* W_xproj = (const float*)d_in[4];  // [2048, 96]
    const float* W_dt    = (const float*)d_in[5];  // [64, 2048]
    const float* b_dt    = (const float*)d_in[6];  // [2048]
    const float* A_log   = (const float*)d_in[7];  // [2048, 16]
    const float* D_skip  = (const float*)d_in[8];  // [2048]
    const float* W_out   = (const float*)d_in[9];  // [2048, 1024]
    float* out = (float*)d_out;                    // [2,1024,1024]

    float* xz;    cudaGetSymbolAddress((void**)&xz,    g_xz);
    float* u;     cudaGetSymbolAddress((void**)&u,     g_u);
    float* xdbl;  cudaGetSymbolAddress((void**)&xdbl,  g_xdbl);
    float* xpart; cudaGetSymbolAddress((void**)&xpart, g_xpart);
    float* part;  cudaGetSymbolAddress((void**)&part,  g_part);

    __nv_bfloat16 *xh, *xl, *winTh, *winTl, *yh, *yl, *woutTh, *woutTl;
    cudaGetSymbolAddress((void**)&xh,     g_xh);
    cudaGetSymbolAddress((void**)&xl,     g_xl);
    cudaGetSymbolAddress((void**)&winTh,  g_winT_h);
    cudaGetSymbolAddress((void**)&winTl,  g_winT_l);
    cudaGetSymbolAddress((void**)&yh,     g_yh);
    cudaGetSymbolAddress((void**)&yl,     g_yl);
    cudaGetSymbolAddress((void**)&woutTh, g_woutT_h);
    cudaGetSymbolAddress((void**)&woutTl, g_woutT_l);

    cudaFuncSetAttribute(gemm_mma, cudaFuncAttributeMaxDynamicSharedMemorySize, GM_SMEM);
    cudaFuncSetAttribute(scan_kernel, cudaFuncAttributeMaxDynamicSharedMemorySize, SCAN_SMEM);

    // operand conversions
    split_fp32_bf16<<<(MROWS * DMODEL) / 256, 256>>>(x, xh, xl, MROWS * DMODEL);
    tsplit_fp32_bf16<<<dim3(4096 / 32, DMODEL / 32), 256>>>(W_in, winTh, winTl, DMODEL, 4096);
    tsplit_fp32_bf16<<<dim3(DMODEL / 32, DINNER / 32), 256>>>(W_out, woutTh, woutTl, DINNER, DMODEL);

    // 1) xz = x @ W_in        [2048,1024] @ [1024,4096]   (tensor cores)
    gemm_mma<<<dim3(4096 / 128, MROWS / 128, 1), 256, GM_SMEM>>>(
        xh, xl, winTh, winTl, xz, DMODEL, 4096, DMODEL, 0);

    // 2) u = silu(conv(xz[:, :2048]) + conv_b)
    conv_silu_kernel<<<(MROWS * DINNER / 4 + 255) / 256, 256>>>(xz, conv_w, conv_b, u);

    // 3) xdbl = u @ W_xproj   (16-way deterministic split-K)
    xprojA<<<dim3(KSPLITS, MROWS / 64), 256>>>(u, W_xproj, xpart);
    xprojB<<<(MROWS * XPROJ_N + 255) / 256, 256>>>(xpart, xdbl);

    // 4+5) fused delta + selective scan -> yh/yl (bf16 split)
    scan_kernel<<<dim3(DINNER / 16, BB), 256, SCAN_SMEM>>>(
        u, xz, xdbl, W_dt, b_dt, A_log, D_skip, yh, yl);

    // 6) out = y @ W_out   [2048,2048]@[2048,1024], 2-way split-K + reduce
    gemm_mma<<<dim3(1024 / 128, MROWS / 128, 2), 256, GM_SMEM>>>(
        yh, yl, woutTh, woutTl, part, DINNER, 1024, 1024,
        (size_t)MROWS * DMODEL);
    reduce2<<<(MROWS * DMODEL / 4 + 255) / 256, 256>>>(part, out, MROWS * DMODEL);
}

// round 14
// speedup vs baseline: 1.2678x; 1.1597x over previous
#include <cuda_runtime.h>
#include <cuda_fp16.h>
#include <cuda_bf16.h>
#include <math.h>
#include <cstdint>

// ---------------------------------------------------------------------------
// TemporalMamba: B=2, L=1024, D_MODEL=1024, D_INNER=2048, D_STATE=16,
// D_CONV=4, DT_RANK=64.
// Tensor cores via mma.sync.m16n8k16 fp16x2 split:
//   C = A(fp16) @ (Wh + Wl)^T,  A single-rounded fp16, W split hi/lo fp16.
//   Error ~2^-11 random-walk ≈ 3-5e-4 rel (gate 1e-3).
// (toolchain is compute_100 base: tcgen05 unavailable)
// ---------------------------------------------------------------------------

#define BB       2
#define LL       1024
#define DMODEL   1024
#define DINNER   2048
#define DSTATE   16
#define DTRANK   64
#define MROWS    (BB * LL)                  // 2048
#define XPROJ_N  (DTRANK + 2 * DSTATE)      // 96
#define KSPLITS  16

// ------------------------- scratch (device globals) ------------------------
__device__ float g_xz[MROWS * 2 * DINNER];      // [M, 4096]
__device__ float g_u[MROWS * DINNER];           // [M, 2048]
__device__ float g_xdbl[MROWS * XPROJ_N];       // [M, 96]
__device__ float g_xpart[KSPLITS * MROWS * XPROJ_N];
__device__ float g_part[2 * MROWS * DMODEL];    // GEMM4 split-K partials

// fp16 operands
__device__ __half g_xh[MROWS * DMODEL];          // x fp16    [2048,1024]
__device__ __half g_winT_h[4096 * DMODEL];       // W_in^T hi [4096,1024]
__device__ __half g_winT_l[4096 * DMODEL];       //        lo
__device__ __half g_yh[MROWS * DINNER];          // y fp16    [2048,2048]
__device__ __half g_woutT_h[DMODEL * DINNER];    // W_out^T hi [1024,2048]
__device__ __half g_woutT_l[DMODEL * DINNER];

// ---------------------------------------------------------------------------
// mma.sync / ldmatrix / cp.async helpers
// ---------------------------------------------------------------------------
__device__ __forceinline__ uint32_t smem_u32(const void* p) {
    uint32_t a;
    asm("{ .reg .u64 t; cvta.to.shared.u64 t, %1; cvt.u32.u64 %0, t; }" : "=r"(a) : "l"(p));
    return a;
}
__device__ __forceinline__ void cpa16(uint32_t s, const void* g) {
    asm volatile("cp.async.cg.shared.global [%0], [%1], 16;" :: "r"(s), "l"(g));
}
__device__ __forceinline__ void ldsm4(uint32_t& r0, uint32_t& r1, uint32_t& r2, uint32_t& r3,
                                      uint32_t addr) {
    asm volatile("ldmatrix.sync.aligned.m8n8.x4.shared.b16 {%0,%1,%2,%3}, [%4];"
                 : "=r"(r0), "=r"(r1), "=r"(r2), "=r"(r3) : "r"(addr));
}
__device__ __forceinline__ void mma16816(float& c0, float& c1, float& c2, float& c3,
                                         uint32_t a0, uint32_t a1, uint32_t a2, uint32_t a3,
                                         uint32_t b0, uint32_t b1) {
    asm volatile(
        "mma.sync.aligned.m16n8k16.row.col.f32.f16.f16.f32 "
        "{%0,%1,%2,%3}, {%4,%5,%6,%7}, {%8,%9}, {%0,%1,%2,%3};"
        : "+f"(c0), "+f"(c1), "+f"(c2), "+f"(c3)
        : "r"(a0), "r"(a1), "r"(a2), "r"(a3), "r"(b0), "r"(b1));
}

// ---------------------------------------------------------------------------
// fp16x2 split tensor-core GEMM:  C[M,N] = A[M,K] @ (Bh+Bl)^T
//   A row-major fp16 [M][K], B as Bt[N][K] (K-major) fp16 hi/lo.
//   CTA: 256 thr = 8 warps (2 M x 4 N), tile 128x128, warp 64x32, BK=32,
//   cp.async double buffer (3 tiles/stage), 2 CTAs/SM.
//   gridDim.z splits K deterministically; z writes C + z*partStride.
// ---------------------------------------------------------------------------
#define SSTR     40                                  // smem row stride (fp16)
#define TILE_B   (128 * SSTR * 2)                    // 10240 B per tile
#define STAGE_B  (3 * TILE_B)                        // A, Bh, Bl
#define GM_SMEM  (2 * STAGE_B)                       // 61440 B

__device__ __forceinline__ void load_stage_tile(
    const __half* __restrict__ G, int rowBase, int k0, int K,
    uint32_t sdst, int tid)
{
#pragma unroll
    for (int i = 0; i < 2; i++) {
        int idx = tid + i * 256;            // 0..511
        int r = idx >> 2;                   // row 0..127
        int q = idx & 3;                    // 16B chunk in 64B row
        const void* g = G + (size_t)(rowBase + r) * K + k0 + q * 8;
        cpa16(sdst + (uint32_t)(r * SSTR + q * 8) * 2, g);
    }
}

__global__ __launch_bounds__(256, 2)
void gemm_mma(const __half* __restrict__ A,
              const __half* __restrict__ Bh, const __half* __restrict__ Bl,
              float* __restrict__ C, int Kfull, int ldc, int kdepth,
              size_t partStride)
{
    extern __shared__ __align__(16) char dsm[];
    const uint32_t sbase = smem_u32(dsm);

    const int tid  = threadIdx.x;
    const int wid  = tid >> 5;
    const int lane = tid & 31;
    const int wm   = wid >> 2;              // 0..1  (M)
    const int wn   = wid & 3;               // 0..3  (N)
    const int bx   = blockIdx.x, by = blockIdx.y;
    const int kbase = blockIdx.z * kdepth;
    C += (size_t)blockIdx.z * partStride;

    const int aRow  = lane & 15;
    const int aCsel = (lane >> 4) * 8;
    const int bRow  = (lane & 7) + ((lane >> 4) << 3);
    const int bCsel = ((lane >> 3) & 1) * 8;

    float acc[4][4][4];
#pragma unroll
    for (int i = 0; i < 4; i++)
#pragma unroll
        for (int j = 0; j < 4; j++)
#pragma unroll
            for (int v = 0; v < 4; v++) acc[i][j][v] = 0.f;

    const int NC = kdepth >> 5;

    load_stage_tile(A,  by * 128, kbase, Kfull, sbase + 0 * TILE_B, tid);
    load_stage_tile(Bh, bx * 128, kbase, Kfull, sbase + 1 * TILE_B, tid);
    load_stage_tile(Bl, bx * 128, kbase, Kfull, sbase + 2 * TILE_B, tid);
    asm volatile("cp.async.commit_group;");

    for (int c = 0; c < NC; c++) {
        if (c + 1 < NC) {
            const uint32_t sd = sbase + ((c + 1) & 1) * STAGE_B;
            const int k0 = kbase + ((c + 1) << 5);
            load_stage_tile(A,  by * 128, k0, Kfull, sd + 0 * TILE_B, tid);
            load_stage_tile(Bh, bx * 128, k0, Kfull, sd + 1 * TILE_B, tid);
            load_stage_tile(Bl, bx * 128, k0, Kfull, sd + 2 * TILE_B, tid);
            asm volatile("cp.async.commit_group;");
            asm volatile("cp.async.wait_group 1;");
        } else {
            asm volatile("cp.async.wait_group 0;");
        }
        __syncthreads();

        const uint32_t st  = sbase + (c & 1) * STAGE_B;
        const uint32_t sA  = st;
        const uint32_t sBh = st + 1 * TILE_B;
        const uint32_t sBl = st + 2 * TILE_B;

#pragma unroll
        for (int kk = 0; kk < 32; kk += 16) {
            uint32_t a[4][4], bh[2][4], bl[2][4];
#pragma unroll
            for (int i = 0; i < 4; i++) {
                uint32_t off = (uint32_t)((wm * 64 + i * 16 + aRow) * SSTR + kk + aCsel) * 2;
                ldsm4(a[i][0], a[i][1], a[i][2], a[i][3], sA + off);
            }
#pragma unroll
            for (int j2 = 0; j2 < 2; j2++) {
                uint32_t off = (uint32_t)((wn * 32 + j2 * 16 + bRow) * SSTR + kk + bCsel) * 2;
                ldsm4(bh[j2][0], bh[j2][1], bh[j2][2], bh[j2][3], sBh + off);
            }
            // A * Bh
#pragma unroll
            for (int i = 0; i < 4; i++)
#pragma unroll
                for (int j = 0; j < 4; j++) {
                    const uint32_t* b = bh[j >> 1] + (j & 1) * 2;
                    mma16816(acc[i][j][0], acc[i][j][1], acc[i][j][2], acc[i][j][3],
                             a[i][0], a[i][1], a[i][2], a[i][3], b[0], b[1]);
                }
            // A * Bl
#pragma unroll
            for (int j2 = 0; j2 < 2; j2++) {
                uint32_t off = (uint32_t)((wn * 32 + j2 * 16 + bRow) * SSTR + kk + bCsel) * 2;
                ldsm4(bl[j2][0], bl[j2][1], bl[j2][2], bl[j2][3], sBl + off);
            }
#pragma unroll
            for (int i = 0; i < 4; i++)
#pragma unroll
                for (int j = 0; j < 4; j++) {
                    const uint32_t* b = bl[j >> 1] + (j & 1) * 2;
                    mma16816(acc[i][j][0], acc[i][j][1], acc[i][j][2], acc[i][j][3],
                             a[i][0], a[i][1], a[i][2], a[i][3], b[0], b[1]);
                }
        }
        __syncthreads();
    }

    const int mBase = by * 128 + wm * 64;
    const int nBase = bx * 128 + wn * 32;
    const int r0 = lane >> 2;
    const int c0 = (lane & 3) * 2;
#pragma unroll
    for (int i = 0; i < 4; i++) {
#pragma unroll
        for (int j = 0; j < 4; j++) {
            float* p0 = C + (size_t)(mBase + i * 16 + r0) * ldc + nBase + j * 8 + c0;
            *(float2*)p0                     = make_float2(acc[i][j][0], acc[i][j][1]);
            *(float2*)(p0 + (size_t)8 * ldc) = make_float2(acc[i][j][2], acc[i][j][3]);
        }
    }
}

// fixed-order split-K reduce: out = part[0..n) + part[n..2n)  (float4)
__global__ __launch_bounds__(256)
void reduce2(const float* __restrict__ part, float* __restrict__ out, int n)
{
    int i = (blockIdx.x * 256 + threadIdx.x) * 4;
    if (i >= n) return;
    float4 a = *(const float4*)(part + i);
    float4 b = *(const float4*)(part + (size_t)n + i);
    float4 r = make_float4(a.x + b.x, a.y + b.y, a.z + b.z, a.w + b.w);
    *(float4*)(out + i) = r;
}

// ---------------------------------------------------------------------------
// fp32 -> fp16 convert (row-major, float4 vectorized)
// ---------------------------------------------------------------------------
__global__ __launch_bounds__(256)
void conv_fp16(const float* __restrict__ in, __half* __restrict__ out, int n4)
{
    int i = blockIdx.x * 256 + threadIdx.x;
    if (i >= n4) return;
    float4 v = *(const float4*)(in + i * 4);
    __half2* p = (__half2*)(out + i * 4);
    p[0] = __half2(__float2half(v.x), __float2half(v.y));
    p[1] = __half2(__float2half(v.z), __float2half(v.w));
}

// transpose + fp16 hi/lo split:  in[K][N] fp32  ->  hiT/loT [N][K] fp16
__global__ __launch_bounds__(256)
void tsplit_fp16(const float* __restrict__ in,
                 __half* __restrict__ hiT, __half* __restrict__ loT,
                 int K, int N)
{
    __shared__ float t[32][33];
    int tx = threadIdx.x & 31;
    int ty = threadIdx.x >> 5;
    int n0 = blockIdx.x * 32;
    int k0 = blockIdx.y * 32;
#pragma unroll
    for (int j = 0; j < 4; j++) {
        int kk = ty + j * 8;
        t[kk][tx] = in[(size_t)(k0 + kk) * N + n0 + tx];
    }
    __syncthreads();
#pragma unroll
    for (int j = 0; j < 4; j++) {
        int a = ty + j * 8;
        float v = t[tx][a];
        __half h = __float2half(v);
        hiT[(size_t)(n0 + a) * K + k0 + tx] = h;
        loT[(size_t)(n0 + a) * K + k0 + tx] = __float2half(v - __half2float(h));
    }
}

// ---------------------------------------------------------------------------
// depthwise conv(4) + bias + silu, float4-vectorized over channels
// ---------------------------------------------------------------------------
__global__ __launch_bounds__(256)
void conv_silu_kernel(const float* __restrict__ xz,
                      const float* __restrict__ cw,
                      const float* __restrict__ cb,
                      float* __restrict__ u)
{
    int idx = blockIdx.x * blockDim.x + threadIdx.x;
    if (idx >= MROWS * DINNER / 4) return;
    int d4  = (idx & (DINNER / 4 - 1)) * 4;
    int row = idx >> 9;
    int l   = row & (LL - 1);

    float4 w0 = *(const float4*)(cw + d4 * 4 + 0);
    float4 w1 = *(const float4*)(cw + d4 * 4 + 4);
    float4 w2 = *(const float4*)(cw + d4 * 4 + 8);
    float4 w3 = *(const float4*)(cw + d4 * 4 + 12);
    float4 bias = *(const float4*)(cb + d4);

    const float* base = xz + (size_t)row * (2 * DINNER) + d4;
    const int stride = 2 * DINNER;

    float4 s = bias;
    if (l >= 3) {
        float4 v = *(const float4*)(base - 3 * stride);
        s.x += v.x * w0.x; s.y += v.y * w1.x; s.z += v.z * w2.x; s.w += v.w * w3.x;
    }
    if (l >= 2) {
        float4 v = *(const float4*)(base - 2 * stride);
        s.x += v.x * w0.y; s.y += v.y * w1.y; s.z += v.z * w2.y; s.w += v.w * w3.y;
    }
    if (l >= 1) {
        float4 v = *(const float4*)(base - 1 * stride);
        s.x += v.x * w0.z; s.y += v.y * w1.z; s.z += v.z * w2.z; s.w += v.w * w3.z;
    }
    {
        float4 v = *(const float4*)(base);
        s.x += v.x * w0.w; s.y += v.y * w1.w; s.z += v.z * w2.w; s.w += v.w * w3.w;
    }
    float4 r;
    r.x = s.x / (1.f + expf(-s.x));
    r.y = s.y / (1.f + expf(-s.y));
    r.z = s.z / (1.f + expf(-s.z));
    r.w = s.w / (1.f + expf(-s.w));
    *(float4*)(u + (size_t)row * DINNER + d4) = r;
}

// ---------------------------------------------------------------------------
// xproj split-K (16-way):  part[ks] = u[:, ks*128:(ks+1)*128] @ W_xproj[...]
// ---------------------------------------------------------------------------
#define XKD (DINNER / KSPLITS)             // 128 K per split
__global__ __launch_bounds__(256)
void xprojA(const float* __restrict__ u, const float* __restrict__ W,
            float* __restrict__ part)
{
    __shared__ float As[64 * 32];
    __shared__ float Bs[96 * 36];

    const int ks = blockIdx.x;
    const int mb = blockIdx.y;
    const int tid = threadIdx.x;
    const int rg = tid >> 4;
    const int cg = tid & 15;

    float acc[4][6];
#pragma unroll
    for (int r = 0; r < 4; r++)
#pragma unroll
        for (int j = 0; j < 6; j++) acc[r][j] = 0.f;

    for (int kc = 0; kc < XKD / 32; kc++) {
        const int kbase = ks * XKD + kc * 32;
#pragma unroll
        for (int i = tid; i < 64 * 32; i += 256) {
            int r = i >> 5, k = i & 31;
            As[r * 32 + k] = u[(size_t)(mb * 64 + r) * DINNER + kbase + k];
        }
#pragma unroll
        for (int i = tid; i < 96 * 32; i += 256) {
            int c = i % 96, k = i / 96;
            Bs[c * 36 + k] = W[(size_t)(kbase + k) * XPROJ_N + c];
        }
        __syncthreads();
#pragma unroll
        for (int kq = 0; kq < 8; kq++) {
            float4 a[4], b[6];
#pragma unroll
            for (int r = 0; r < 4; r++)
                a[r] = *(const float4*)&As[(rg * 4 + r) * 32 + kq * 4];
#pragma unroll
            for (int j = 0; j < 6; j++)
                b[j] = *(const float4*)&Bs[(j * 16 + cg) * 36 + kq * 4];
#pragma unroll
            for (int r = 0; r < 4; r++)
#pragma unroll
                for (int j = 0; j < 6; j++)
                    acc[r][j] += a[r].x * b[j].x + a[r].y * b[j].y
                               + a[r].z * b[j].z + a[r].w * b[j].w;
        }
        __syncthreads();
    }
#pragma unroll
    for (int r = 0; r < 4; r++)
#pragma unroll
        for (int j = 0; j < 6; j++)
            part[((size_t)ks * MROWS + mb * 64 + rg * 4 + r) * XPROJ_N + j * 16 + cg]
                = acc[r][j];
}

__global__ __launch_bounds__(256)
void xprojB(const float* __restrict__ part, float* __restrict__ xdbl)
{
    int idx = blockIdx.x * 256 + threadIdx.x;
    if (idx >= MROWS * XPROJ_N) return;
    float s = 0.f;
#pragma unroll
    for (int ks = 0; ks < KSPLITS; ks++)
        s += part[(size_t)ks * MROWS * XPROJ_N + idx];
    xdbl[idx] = s;
}

// ---------------------------------------------------------------------------
// selective scan (R8 structure — measured best); outputs y as fp16 single.
// ---------------------------------------------------------------------------
#define SCT 32
#define OFF_W     0                       // [64][16]     1024
#define OFF_BD    1024                    // [16]
#define OFF_DSK   1040                    // [16]
#define OFF_DT    1056                    // [32][64]     2048
#define OFF_DEL   3104                    // [32][16]     512
#define OFF_U     3616                    // [32][16]     512
#define OFF_Z     4128                    // [32][16]     512
#define OFF_B     4640                    // [32][16]     512
#define OFF_C     5152                    // [32][16]     512
#define OFF_P     5664                    // [32][16][17] 8704
#define SCAN_SMEM ((5664 + 8704) * 4)     // 57472 bytes

__global__ __launch_bounds__(256)
void scan_kernel(const float* __restrict__ u,
                 const float* __restrict__ xz,
                 const float* __restrict__ xdbl,
                 const float* __restrict__ W_dt,   // [64, 2048]
                 const float* __restrict__ b_dt,   // [2048]
                 const float* __restrict__ A_log,
                 const float* __restrict__ Dskip,
                 __half* __restrict__ yh)
{
    extern __shared__ float sm[];
    float* sW   = sm + OFF_W;
    float* sbd  = sm + OFF_BD;
    float* sdsk = sm + OFF_DSK;
    float* sDT  = sm + OFF_DT;
    float* sDel = sm + OFF_DEL;
    float* sU   = sm + OFF_U;
    float* sZ   = sm + OFF_Z;
    float* sB   = sm + OFF_B;
    float* sC   = sm + OFF_C;
    float* sP   = sm + OFF_P;

    const int tid = threadIdx.x;
    const int tn = tid & 15;
    const int td = tid >> 4;
    const int dbase = blockIdx.x * 16;
    const int b = blockIdx.y;

    for (int i = tid; i < 64 * 16; i += 256) {
        int r = i >> 4, c = i & 15;
        sW[i] = W_dt[(size_t)r * DINNER + dbase + c];
    }
    if (tid < 16) {
        sbd[tid]  = b_dt[dbase + tid];
        sdsk[tid] = Dskip[dbase + tid];
    }
    const float Aq = -expf(A_log[(dbase + td) * DSTATE + tn]);
    __syncthreads();

    float h = 0.f;

    for (int t0 = 0; t0 < LL; t0 += SCT) {
        // ---- stage ----
#pragma unroll
        for (int i = tid; i < SCT * 16; i += 256) {
            int r = i >> 4, c = i & 15;
            int row = b * LL + t0 + r;
            sU[i] = u[(size_t)row * DINNER + dbase + c];
            sZ[i] = xz[(size_t)row * (2 * DINNER) + DINNER + dbase + c];
            sB[i] = xdbl[(size_t)row * XPROJ_N + DTRANK + c];
            sC[i] = xdbl[(size_t)row * XPROJ_N + DTRANK + DSTATE + c];
        }
#pragma unroll
        for (int i = tid; i < SCT * 64; i += 256) {
            int r = i >> 6, k = i & 63;
            sDT[i] = xdbl[(size_t)(b * LL + t0 + r) * XPROJ_N + k];
        }
        __syncthreads();

        // ---- fused delta ----
        {
            const int c = tid & 15;
            const int r0 = tid >> 4;
            float s0 = sbd[c], s1 = sbd[c];
#pragma unroll 8
            for (int k = 0; k < 64; k++) {
                float w = sW[k * 16 + c];
                s0 += sDT[r0 * 64 + k] * w;
                s1 += sDT[(r0 + 16) * 64 + k] * w;
            }
            sDel[r0 * 16 + c]        = (s0 > 20.f) ? s0 : log1pf(expf(s0));
            sDel[(r0 + 16) * 16 + c] = (s1 > 20.f) ? s1 : log1pf(expf(s1));
        }
        __syncthreads();

        // ---- serial recurrence: critical path = 1 FFMA/step ----
#pragma unroll 8
        for (int tt = 0; tt < SCT; tt++) {
            float dlt = sDel[tt * 16 + td];
            float uu  = sU[tt * 16 + td];
            float bb  = sB[tt * 16 + tn];
            float cc  = sC[tt * 16 + tn];
            float dA  = __expf(dlt * Aq);
            h = dA * h + (dlt * uu) * bb;
            sP[(tt * 16 + td) * 17 + tn] = h * cc;
        }
        __syncthreads();

        // ---- parallel reduce over n + gate + fp16 output ----
#pragma unroll
        for (int v = 0; v < 2; v++) {
            int o = tid + v * 256;
            int tt = o >> 4, c = o & 15;
            const float* p = sP + (tt * 16 + c) * 17;
            float s = 0.f;
#pragma unroll
            for (int n = 0; n < 16; n++) s += p[n];
            float uu = sU[tt * 16 + c];
            float zz = sZ[tt * 16 + c];
            float yv = s + sdsk[c] * uu;
            yv *= zz / (1.f + expf(-zz));
            int row = b * LL + t0 + tt;
            yh[(size_t)row * DINNER + dbase + c] = __float2half(yv);
        }
        __syncthreads();
    }
}

// ---------------------------------------------------------------------------
extern "C" void kernel_launch(void* const* d_in, const int* in_sizes, int n_in,
                              void* d_out, int out_size)
{
    const float* x       = (const float*)d_in[0];  // [2,1024,1024]
    const float* W_in    = (const float*)d_in[1];  // [1024, 4096]
    const float* conv_w  = (const float*)d_in[2];  // [2048, 1, 4]
    const float* conv_b  = (const float*)d_in[3];  // [2048]
    const float* W_xproj = (const float*)d_in[4];  // [2048, 96]
    const float* W_dt    = (const float*)d_in[5];  // [64, 2048]
    const float* b_dt    = (const float*)d_in[6];  // [2048]
    const float* A_log   = (const float*)d_in[7];  // [2048, 16]
    const float* D_skip  = (const float*)d_in[8];  // [2048]
    const float* W_out   = (const float*)d_in[9];  // [2048, 1024]
    float* out = (float*)d_out;                    // [2,1024,1024]

    float* xz;    cudaGetSymbolAddress((void**)&xz,    g_xz);
    float* u;     cudaGetSymbolAddress((void**)&u,     g_u);
    float* xdbl;  cudaGetSymbolAddress((void**)&xdbl,  g_xdbl);
    float* xpart; cudaGetSymbolAddress((void**)&xpart, g_xpart);
    float* part;  cudaGetSymbolAddress((void**)&part,  g_part);

    __half *xh, *winTh, *winTl, *yh, *woutTh, *woutTl;
    cudaGetSymbolAddress((void**)&xh,     g_xh);
    cudaGetSymbolAddress((void**)&winTh,  g_winT_h);
    cudaGetSymbolAddress((void**)&winTl,  g_winT_l);
    cudaGetSymbolAddress((void**)&yh,     g_yh);
    cudaGetSymbolAddress((void**)&woutTh, g_woutT_h);
    cudaGetSymbolAddress((void**)&woutTl, g_woutT_l);

    cudaFuncSetAttribute(gemm_mma, cudaFuncAttributeMaxDynamicSharedMemorySize, GM_SMEM);
    cudaFuncSetAttribute(scan_kernel, cudaFuncAttributeMaxDynamicSharedMemorySize, SCAN_SMEM);

    // operand conversions
    conv_fp16<<<(MROWS * DMODEL / 4) / 256, 256>>>(x, xh, MROWS * DMODEL / 4);
    tsplit_fp16<<<dim3(4096 / 32, DMODEL / 32), 256>>>(W_in, winTh, winTl, DMODEL, 4096);
    tsplit_fp16<<<dim3(DMODEL / 32, DINNER / 32), 256>>>(W_out, woutTh, woutTl, DINNER, DMODEL);

    // 1) xz = x @ W_in        [2048,1024] @ [1024,4096]   (tensor cores)
    gemm_mma<<<dim3(4096 / 128, MROWS / 128, 1), 256, GM_SMEM>>>(
        xh, winTh, winTl, xz, DMODEL, 4096, DMODEL, 0);

    // 2) u = silu(conv(xz[:, :2048]) + conv_b)
    conv_silu_kernel<<<(MROWS * DINNER / 4 + 255) / 256, 256>>>(xz, conv_w, conv_b, u);

    // 3) xdbl = u @ W_xproj   (16-way deterministic split-K)
    xprojA<<<dim3(KSPLITS, MROWS / 64), 256>>>(u, W_xproj, xpart);
    xprojB<<<(MROWS * XPROJ_N + 255) / 256, 256>>>(xpart, xdbl);

    // 4+5) fused delta + selective scan -> yh (fp16)
    scan_kernel<<<dim3(DINNER / 16, BB), 256, SCAN_SMEM>>>(
        u, xz, xdbl, W_dt, b_dt, A_log, D_skip, yh);

    // 6) out = y @ W_out   [2048,2048]@[2048,1024], 2-way split-K + reduce
    gemm_mma<<<dim3(1024 / 128, MROWS / 128, 2), 256, GM_SMEM>>>(
        yh, woutTh, woutTl, part, DINNER, 1024, 1024,
        (size_t)MROWS * DMODEL);
    reduce2<<<(MROWS * DMODEL / 4 + 255) / 256, 256>>>(part, out, MROWS * DMODEL);
}

// round 15
// speedup vs baseline: 1.3318x; 1.0505x over previous
#include <cuda_runtime.h>
#include <cuda_fp16.h>
#include <cuda_bf16.h>
#include <math.h>
#include <cstdint>

// ---------------------------------------------------------------------------
// TemporalMamba: B=2, L=1024, D_MODEL=1024, D_INNER=2048, D_STATE=16,
// D_CONV=4, DT_RANK=64.
// Tensor cores via mma.sync.m16n8k16 fp16x2 split:
//   C = A(fp16) @ (Wh + Wl)^T,  A single-rounded fp16, W split hi/lo fp16.
//   Measured rel_err 3.6e-4 (gate 1e-3).
// (toolchain is compute_100 base: tcgen05 unavailable)
// ---------------------------------------------------------------------------

#define BB       2
#define LL       1024
#define DMODEL   1024
#define DINNER   2048
#define DSTATE   16
#define DTRANK   64
#define MROWS    (BB * LL)                  // 2048
#define XPROJ_N  (DTRANK + 2 * DSTATE)      // 96
#define KSPLITS  16

// ------------------------- scratch (device globals) ------------------------
__device__ float g_xz[MROWS * 2 * DINNER];      // [M, 4096]
__device__ float g_u[MROWS * DINNER];           // [M, 2048]
__device__ float g_xdbl[MROWS * XPROJ_N];       // [M, 96]
__device__ float g_xpart[KSPLITS * MROWS * XPROJ_N];
__device__ float g_part[2 * MROWS * DMODEL];    // GEMM4 split-K partials

// fp16 operands
__device__ __half g_xh[MROWS * DMODEL];          // x fp16    [2048,1024]
__device__ __half g_winT_h[4096 * DMODEL];       // W_in^T hi [4096,1024]
__device__ __half g_winT_l[4096 * DMODEL];       //        lo
__device__ __half g_yh[MROWS * DINNER];          // y fp16    [2048,2048]
__device__ __half g_woutT_h[DMODEL * DINNER];    // W_out^T hi [1024,2048]
__device__ __half g_woutT_l[DMODEL * DINNER];

// ---------------------------------------------------------------------------
// mma.sync / ldmatrix / cp.async helpers
// ---------------------------------------------------------------------------
__device__ __forceinline__ uint32_t smem_u32(const void* p) {
    uint32_t a;
    asm("{ .reg .u64 t; cvta.to.shared.u64 t, %1; cvt.u32.u64 %0, t; }" : "=r"(a) : "l"(p));
    return a;
}
__device__ __forceinline__ void cpa16(uint32_t s, const void* g) {
    asm volatile("cp.async.cg.shared.global [%0], [%1], 16;" :: "r"(s), "l"(g));
}
__device__ __forceinline__ void ldsm4(uint32_t& r0, uint32_t& r1, uint32_t& r2, uint32_t& r3,
                                      uint32_t addr) {
    asm volatile("ldmatrix.sync.aligned.m8n8.x4.shared.b16 {%0,%1,%2,%3}, [%4];"
                 : "=r"(r0), "=r"(r1), "=r"(r2), "=r"(r3) : "r"(addr));
}
__device__ __forceinline__ void mma16816(float& c0, float& c1, float& c2, float& c3,
                                         uint32_t a0, uint32_t a1, uint32_t a2, uint32_t a3,
                                         uint32_t b0, uint32_t b1) {
    asm volatile(
        "mma.sync.aligned.m16n8k16.row.col.f32.f16.f16.f32 "
        "{%0,%1,%2,%3}, {%4,%5,%6,%7}, {%8,%9}, {%0,%1,%2,%3};"
        : "+f"(c0), "+f"(c1), "+f"(c2), "+f"(c3)
        : "r"(a0), "r"(a1), "r"(a2), "r"(a3), "r"(b0), "r"(b1));
}

// ---------------------------------------------------------------------------
// fp16x2 split tensor-core GEMM:  C[M,N] = A[M,K] @ (Bh+Bl)^T
//   A row-major fp16 [M][K], B as Bt[N][K] (K-major) fp16 hi/lo.
//   CTA: 256 thr = 8 warps (2 M x 4 N), tile 128x128, warp 64x32, BK=64,
//   cp.async double buffer (3 tiles/stage, 110.6KB), 2 CTAs/SM.
//   gridDim.z splits K deterministically; z writes C + z*partStride.
// ---------------------------------------------------------------------------
#define SSTR     72                                  // smem row stride (fp16)
#define TILE_B   (128 * SSTR * 2)                    // 18432 B per tile
#define STAGE_B  (3 * TILE_B)                        // A, Bh, Bl = 55296 B
#define GM_SMEM  (2 * STAGE_B)                       // 110592 B

__device__ __forceinline__ void load_stage_tile(
    const __half* __restrict__ G, int rowBase, int k0, int K,
    uint32_t sdst, int tid)
{
#pragma unroll
    for (int i = 0; i < 4; i++) {
        int idx = tid + i * 256;            // 0..1023
        int r = idx >> 3;                   // row 0..127
        int q = idx & 7;                    // 16B chunk in 128B row
        const void* g = G + (size_t)(rowBase + r) * K + k0 + q * 8;
        cpa16(sdst + (uint32_t)(r * SSTR + q * 8) * 2, g);
    }
}

__global__ __launch_bounds__(256, 2)
void gemm_mma(const __half* __restrict__ A,
              const __half* __restrict__ Bh, const __half* __restrict__ Bl,
              float* __restrict__ C, int Kfull, int ldc, int kdepth,
              size_t partStride)
{
    extern __shared__ __align__(16) char dsm[];
    const uint32_t sbase = smem_u32(dsm);

    const int tid  = threadIdx.x;
    const int wid  = tid >> 5;
    const int lane = tid & 31;
    const int wm   = wid >> 2;              // 0..1  (M)
    const int wn   = wid & 3;               // 0..3  (N)
    const int bx   = blockIdx.x, by = blockIdx.y;
    const int kbase = blockIdx.z * kdepth;
    C += (size_t)blockIdx.z * partStride;

    const int aRow  = lane & 15;
    const int aCsel = (lane >> 4) * 8;
    const int bRow  = (lane & 7) + ((lane >> 4) << 3);
    const int bCsel = ((lane >> 3) & 1) * 8;

    float acc[4][4][4];
#pragma unroll
    for (int i = 0; i < 4; i++)
#pragma unroll
        for (int j = 0; j < 4; j++)
#pragma unroll
            for (int v = 0; v < 4; v++) acc[i][j][v] = 0.f;

    const int NC = kdepth >> 6;

    load_stage_tile(A,  by * 128, kbase, Kfull, sbase + 0 * TILE_B, tid);
    load_stage_tile(Bh, bx * 128, kbase, Kfull, sbase + 1 * TILE_B, tid);
    load_stage_tile(Bl, bx * 128, kbase, Kfull, sbase + 2 * TILE_B, tid);
    asm volatile("cp.async.commit_group;");

    for (int c = 0; c < NC; c++) {
        if (c + 1 < NC) {
            const uint32_t sd = sbase + ((c + 1) & 1) * STAGE_B;
            const int k0 = kbase + ((c + 1) << 6);
            load_stage_tile(A,  by * 128, k0, Kfull, sd + 0 * TILE_B, tid);
            load_stage_tile(Bh, bx * 128, k0, Kfull, sd + 1 * TILE_B, tid);
            load_stage_tile(Bl, bx * 128, k0, Kfull, sd + 2 * TILE_B, tid);
            asm volatile("cp.async.commit_group;");
            asm volatile("cp.async.wait_group 1;");
        } else {
            asm volatile("cp.async.wait_group 0;");
        }
        __syncthreads();

        const uint32_t st  = sbase + (c & 1) * STAGE_B;
        const uint32_t sA  = st;
        const uint32_t sBh = st + 1 * TILE_B;
        const uint32_t sBl = st + 2 * TILE_B;

#pragma unroll
        for (int kk = 0; kk < 64; kk += 16) {
            uint32_t a[4][4], bh[2][4], bl[2][4];
            // all fragment loads up front: bl latency hides under hh MMAs
#pragma unroll
            for (int i = 0; i < 4; i++) {
                uint32_t off = (uint32_t)((wm * 64 + i * 16 + aRow) * SSTR + kk + aCsel) * 2;
                ldsm4(a[i][0], a[i][1], a[i][2], a[i][3], sA + off);
            }
#pragma unroll
            for (int j2 = 0; j2 < 2; j2++) {
                uint32_t off = (uint32_t)((wn * 32 + j2 * 16 + bRow) * SSTR + kk + bCsel) * 2;
                ldsm4(bh[j2][0], bh[j2][1], bh[j2][2], bh[j2][3], sBh + off);
            }
#pragma unroll
            for (int j2 = 0; j2 < 2; j2++) {
                uint32_t off = (uint32_t)((wn * 32 + j2 * 16 + bRow) * SSTR + kk + bCsel) * 2;
                ldsm4(bl[j2][0], bl[j2][1], bl[j2][2], bl[j2][3], sBl + off);
            }
            // A * Bh
#pragma unroll
            for (int i = 0; i < 4; i++)
#pragma unroll
                for (int j = 0; j < 4; j++) {
                    const uint32_t* b = bh[j >> 1] + (j & 1) * 2;
                    mma16816(acc[i][j][0], acc[i][j][1], acc[i][j][2], acc[i][j][3],
                             a[i][0], a[i][1], a[i][2], a[i][3], b[0], b[1]);
                }
            // A * Bl
#pragma unroll
            for (int i = 0; i < 4; i++)
#pragma unroll
                for (int j = 0; j < 4; j++) {
                    const uint32_t* b = bl[j >> 1] + (j & 1) * 2;
                    mma16816(acc[i][j][0], acc[i][j][1], acc[i][j][2], acc[i][j][3],
                             a[i][0], a[i][1], a[i][2], a[i][3], b[0], b[1]);
                }
        }
        __syncthreads();
    }

    const int mBase = by * 128 + wm * 64;
    const int nBase = bx * 128 + wn * 32;
    const int r0 = lane >> 2;
    const int c0 = (lane & 3) * 2;
#pragma unroll
    for (int i = 0; i < 4; i++) {
#pragma unroll
        for (int j = 0; j < 4; j++) {
            float* p0 = C + (size_t)(mBase + i * 16 + r0) * ldc + nBase + j * 8 + c0;
            *(float2*)p0                     = make_float2(acc[i][j][0], acc[i][j][1]);
            *(float2*)(p0 + (size_t)8 * ldc) = make_float2(acc[i][j][2], acc[i][j][3]);
        }
    }
}

// fixed-order split-K reduce: out = part[0..n) + part[n..2n)  (float4)
__global__ __launch_bounds__(256)
void reduce2(const float* __restrict__ part, float* __restrict__ out, int n)
{
    int i = (blockIdx.x * 256 + threadIdx.x) * 4;
    if (i >= n) return;
    float4 a = *(const float4*)(part + i);
    float4 b = *(const float4*)(part + (size_t)n + i);
    float4 r = make_float4(a.x + b.x, a.y + b.y, a.z + b.z, a.w + b.w);
    *(float4*)(out + i) = r;
}

// ---------------------------------------------------------------------------
// fp32 -> fp16 convert (row-major, float4 vectorized)
// ---------------------------------------------------------------------------
__global__ __launch_bounds__(256)
void conv_fp16(const float* __restrict__ in, __half* __restrict__ out, int n4)
{
    int i = blockIdx.x * 256 + threadIdx.x;
    if (i >= n4) return;
    float4 v = *(const float4*)(in + i * 4);
    __half2* p = (__half2*)(out + i * 4);
    p[0] = __half2(__float2half(v.x), __float2half(v.y));
    p[1] = __half2(__float2half(v.z), __float2half(v.w));
}

// transpose + fp16 hi/lo split:  in[K][N] fp32  ->  hiT/loT [N][K] fp16
__global__ __launch_bounds__(256)
void tsplit_fp16(const float* __restrict__ in,
                 __half* __restrict__ hiT, __half* __restrict__ loT,
                 int K, int N)
{
    __shared__ float t[32][33];
    int tx = threadIdx.x & 31;
    int ty = threadIdx.x >> 5;
    int n0 = blockIdx.x * 32;
    int k0 = blockIdx.y * 32;
#pragma unroll
    for (int j = 0; j < 4; j++) {
        int kk = ty + j * 8;
        t[kk][tx] = in[(size_t)(k0 + kk) * N + n0 + tx];
    }
    __syncthreads();
#pragma unroll
    for (int j = 0; j < 4; j++) {
        int a = ty + j * 8;
        float v = t[tx][a];
        __half h = __float2half(v);
        hiT[(size_t)(n0 + a) * K + k0 + tx] = h;
        loT[(size_t)(n0 + a) * K + k0 + tx] = __float2half(v - __half2float(h));
    }
}

// ---------------------------------------------------------------------------
// depthwise conv(4) + bias + silu, float4-vectorized over channels
// ---------------------------------------------------------------------------
__global__ __launch_bounds__(256)
void conv_silu_kernel(const float* __restrict__ xz,
                      const float* __restrict__ cw,
                      const float* __restrict__ cb,
                      float* __restrict__ u)
{
    int idx = blockIdx.x * blockDim.x + threadIdx.x;
    if (idx >= MROWS * DINNER / 4) return;
    int d4  = (idx & (DINNER / 4 - 1)) * 4;
    int row = idx >> 9;
    int l   = row & (LL - 1);

    float4 w0 = *(const float4*)(cw + d4 * 4 + 0);
    float4 w1 = *(const float4*)(cw + d4 * 4 + 4);
    float4 w2 = *(const float4*)(cw + d4 * 4 + 8);
    float4 w3 = *(const float4*)(cw + d4 * 4 + 12);
    float4 bias = *(const float4*)(cb + d4);

    const float* base = xz + (size_t)row * (2 * DINNER) + d4;
    const int stride = 2 * DINNER;

    float4 s = bias;
    if (l >= 3) {
        float4 v = *(const float4*)(base - 3 * stride);
        s.x += v.x * w0.x; s.y += v.y * w1.x; s.z += v.z * w2.x; s.w += v.w * w3.x;
    }
    if (l >= 2) {
        float4 v = *(const float4*)(base - 2 * stride);
        s.x += v.x * w0.y; s.y += v.y * w1.y; s.z += v.z * w2.y; s.w += v.w * w3.y;
    }
    if (l >= 1) {
        float4 v = *(const float4*)(base - 1 * stride);
        s.x += v.x * w0.z; s.y += v.y * w1.z; s.z += v.z * w2.z; s.w += v.w * w3.z;
    }
    {
        float4 v = *(const float4*)(base);
        s.x += v.x * w0.w; s.y += v.y * w1.w; s.z += v.z * w2.w; s.w += v.w * w3.w;
    }
    float4 r;
    r.x = s.x / (1.f + expf(-s.x));
    r.y = s.y / (1.f + expf(-s.y));
    r.z = s.z / (1.f + expf(-s.z));
    r.w = s.w / (1.f + expf(-s.w));
    *(float4*)(u + (size_t)row * DINNER + d4) = r;
}

// ---------------------------------------------------------------------------
// xproj split-K (16-way):  part[ks] = u[:, ks*128:(ks+1)*128] @ W_xproj[...]
// ---------------------------------------------------------------------------
#define XKD (DINNER / KSPLITS)             // 128 K per split
__global__ __launch_bounds__(256)
void xprojA(const float* __restrict__ u, const float* __restrict__ W,
            float* __restrict__ part)
{
    __shared__ float As[64 * 32];
    __shared__ float Bs[96 * 36];

    const int ks = blockIdx.x;
    const int mb = blockIdx.y;
    const int tid = threadIdx.x;
    const int rg = tid >> 4;
    const int cg = tid & 15;

    float acc[4][6];
#pragma unroll
    for (int r = 0; r < 4; r++)
#pragma unroll
        for (int j = 0; j < 6; j++) acc[r][j] = 0.f;

    for (int kc = 0; kc < XKD / 32; kc++) {
        const int kbase = ks * XKD + kc * 32;
#pragma unroll
        for (int i = tid; i < 64 * 32; i += 256) {
            int r = i >> 5, k = i & 31;
            As[r * 32 + k] = u[(size_t)(mb * 64 + r) * DINNER + kbase + k];
        }
#pragma unroll
        for (int i = tid; i < 96 * 32; i += 256) {
            int c = i % 96, k = i / 96;
            Bs[c * 36 + k] = W[(size_t)(kbase + k) * XPROJ_N + c];
        }
        __syncthreads();
#pragma unroll
        for (int kq = 0; kq < 8; kq++) {
            float4 a[4], b[6];
#pragma unroll
            for (int r = 0; r < 4; r++)
                a[r] = *(const float4*)&As[(rg * 4 + r) * 32 + kq * 4];
#pragma unroll
            for (int j = 0; j < 6; j++)
                b[j] = *(const float4*)&Bs[(j * 16 + cg) * 36 + kq * 4];
#pragma unroll
            for (int r = 0; r < 4; r++)
#pragma unroll
                for (int j = 0; j < 6; j++)
                    acc[r][j] += a[r].x * b[j].x + a[r].y * b[j].y
                               + a[r].z * b[j].z + a[r].w * b[j].w;
        }
        __syncthreads();
    }
#pragma unroll
    for (int r = 0; r < 4; r++)
#pragma unroll
        for (int j = 0; j < 6; j++)
            part[((size_t)ks * MROWS + mb * 64 + rg * 4 + r) * XPROJ_N + j * 16 + cg]
                = acc[r][j];
}

__global__ __launch_bounds__(256)
void xprojB(const float* __restrict__ part, float* __restrict__ xdbl)
{
    int idx = blockIdx.x * 256 + threadIdx.x;
    if (idx >= MROWS * XPROJ_N) return;
    float s = 0.f;
#pragma unroll
    for (int ks = 0; ks < KSPLITS; ks++)
        s += part[(size_t)ks * MROWS * XPROJ_N + idx];
    xdbl[idx] = s;
}

// ---------------------------------------------------------------------------
// selective scan (R8 structure — measured best); outputs y as fp16 single.
// ---------------------------------------------------------------------------
#define SCT 32
#define OFF_W     0                       // [64][16]     1024
#define OFF_BD    1024                    // [16]
#define OFF_DSK   1040                    // [16]
#define OFF_DT    1056                    // [32][64]     2048
#define OFF_DEL   3104                    // [32][16]     512
#define OFF_U     3616                    // [32][16]     512
#define OFF_Z     4128                    // [32][16]     512
#define OFF_B     4640                    // [32][16]     512
#define OFF_C     5152                    // [32][16]     512
#define OFF_P     5664                    // [32][16][17] 8704
#define SCAN_SMEM ((5664 + 8704) * 4)     // 57472 bytes

__global__ __launch_bounds__(256)
void scan_kernel(const float* __restrict__ u,
                 const float* __restrict__ xz,
                 const float* __restrict__ xdbl,
                 const float* __restrict__ W_dt,   // [64, 2048]
                 const float* __restrict__ b_dt,   // [2048]
                 const float* __restrict__ A_log,
                 const float* __restrict__ Dskip,
                 __half* __restrict__ yh)
{
    extern __shared__ float sm[];
    float* sW   = sm + OFF_W;
    float* sbd  = sm + OFF_BD;
    float* sdsk = sm + OFF_DSK;
    float* sDT  = sm + OFF_DT;
    float* sDel = sm + OFF_DEL;
    float* sU   = sm + OFF_U;
    float* sZ   = sm + OFF_Z;
    float* sB   = sm + OFF_B;
    float* sC   = sm + OFF_C;
    float* sP   = sm + OFF_P;

    const int tid = threadIdx.x;
    const int tn = tid & 15;
    const int td = tid >> 4;
    const int dbase = blockIdx.x * 16;
    const int b = blockIdx.y;

    for (int i = tid; i < 64 * 16; i += 256) {
        int r = i >> 4, c = i & 15;
        sW[i] = W_dt[(size_t)r * DINNER + dbase + c];
    }
    if (tid < 16) {
        sbd[tid]  = b_dt[dbase + tid];
        sdsk[tid] = Dskip[dbase + tid];
    }
    const float Aq = -expf(A_log[(dbase + td) * DSTATE + tn]);
    __syncthreads();

    float h = 0.f;

    for (int t0 = 0; t0 < LL; t0 += SCT) {
        // ---- stage ----
#pragma unroll
        for (int i = tid; i < SCT * 16; i += 256) {
            int r = i >> 4, c = i & 15;
            int row = b * LL + t0 + r;
            sU[i] = u[(size_t)row * DINNER + dbase + c];
            sZ[i] = xz[(size_t)row * (2 * DINNER) + DINNER + dbase + c];
            sB[i] = xdbl[(size_t)row * XPROJ_N + DTRANK + c];
            sC[i] = xdbl[(size_t)row * XPROJ_N + DTRANK + DSTATE + c];
        }
#pragma unroll
        for (int i = tid; i < SCT * 64; i += 256) {
            int r = i >> 6, k = i & 63;
            sDT[i] = xdbl[(size_t)(b * LL + t0 + r) * XPROJ_N + k];
        }
        __syncthreads();

        // ---- fused delta ----
        {
            const int c = tid & 15;
            const int r0 = tid >> 4;
            float s0 = sbd[c], s1 = sbd[c];
#pragma unroll 8
            for (int k = 0; k < 64; k++) {
                float w = sW[k * 16 + c];
                s0 += sDT[r0 * 64 + k] * w;
                s1 += sDT[(r0 + 16) * 64 + k] * w;
            }
            sDel[r0 * 16 + c]        = (s0 > 20.f) ? s0 : log1pf(expf(s0));
            sDel[(r0 + 16) * 16 + c] = (s1 > 20.f) ? s1 : log1pf(expf(s1));
        }
        __syncthreads();

        // ---- serial recurrence: critical path = 1 FFMA/step ----
#pragma unroll 8
        for (int tt = 0; tt < SCT; tt++) {
            float dlt = sDel[tt * 16 + td];
            float uu  = sU[tt * 16 + td];
            float bb  = sB[tt * 16 + tn];
            float cc  = sC[tt * 16 + tn];
            float dA  = __expf(dlt * Aq);
            h = dA * h + (dlt * uu) * bb;
            sP[(tt * 16 + td) * 17 + tn] = h * cc;
        }
        __syncthreads();

        // ---- parallel reduce over n + gate + fp16 output ----
#pragma unroll
        for (int v = 0; v < 2; v++) {
            int o = tid + v * 256;
            int tt = o >> 4, c = o & 15;
            const float* p = sP + (tt * 16 + c) * 17;
            float s = 0.f;
#pragma unroll
            for (int n = 0; n < 16; n++) s += p[n];
            float uu = sU[tt * 16 + c];
            float zz = sZ[tt * 16 + c];
            float yv = s + sdsk[c] * uu;
            yv *= zz / (1.f + expf(-zz));
            int row = b * LL + t0 + tt;
            yh[(size_t)row * DINNER + dbase + c] = __float2half(yv);
        }
        __syncthreads();
    }
}

// ---------------------------------------------------------------------------
extern "C" void kernel_launch(void* const* d_in, const int* in_sizes, int n_in,
                              void* d_out, int out_size)
{
    const float* x       = (const float*)d_in[0];  // [2,1024,1024]
    const float* W_in    = (const float*)d_in[1];  // [1024, 4096]
    const float* conv_w  = (const float*)d_in[2];  // [2048, 1, 4]
    const float* conv_b  = (const float*)d_in[3];  // [2048]
    const float* W_xproj = (const float*)d_in[4];  // [2048, 96]
    const float* W_dt    = (const float*)d_in[5];  // [64, 2048]
    const float* b_dt    = (const float*)d_in[6];  // [2048]
    const float* A_log   = (const float*)d_in[7];  // [2048, 16]
    const float* D_skip  = (const float*)d_in[8];  // [2048]
    const float* W_out   = (const float*)d_in[9];  // [2048, 1024]
    float* out = (float*)d_out;                    // [2,1024,1024]

    float* xz;    cudaGetSymbolAddress((void**)&xz,    g_xz);
    float* u;     cudaGetSymbolAddress((void**)&u,     g_u);
    float* xdbl;  cudaGetSymbolAddress((void**)&xdbl,  g_xdbl);
    float* xpart; cudaGetSymbolAddress((void**)&xpart, g_xpart);
    float* part;  cudaGetSymbolAddress((void**)&part,  g_part);

    __half *xh, *winTh, *winTl, *yh, *woutTh, *woutTl;
    cudaGetSymbolAddress((void**)&xh,     g_xh);
    cudaGetSymbolAddress((void**)&winTh,  g_winT_h);
    cudaGetSymbolAddress((void**)&winTl,  g_winT_l);
    cudaGetSymbolAddress((void**)&yh,     g_yh);
    cudaGetSymbolAddress((void**)&woutTh, g_woutT_h);
    cudaGetSymbolAddress((void**)&woutTl, g_woutT_l);

    cudaFuncSetAttribute(gemm_mma, cudaFuncAttributeMaxDynamicSharedMemorySize, GM_SMEM);
    cudaFuncSetAttribute(scan_kernel, cudaFuncAttributeMaxDynamicSharedMemorySize, SCAN_SMEM);

    // operand conversions
    conv_fp16<<<(MROWS * DMODEL / 4) / 256, 256>>>(x, xh, MROWS * DMODEL / 4);
    tsplit_fp16<<<dim3(4096 / 32, DMODEL / 32), 256>>>(W_in, winTh, winTl, DMODEL, 4096);
    tsplit_fp16<<<dim3(DMODEL / 32, DINNER / 32), 256>>>(W_out, woutTh, woutTl, DINNER, DMODEL);

    // 1) xz = x @ W_in        [2048,1024] @ [1024,4096]   (tensor cores)
    gemm_mma<<<dim3(4096 / 128, MROWS / 128, 1), 256, GM_SMEM>>>(
        xh, winTh, winTl, xz, DMODEL, 4096, DMODEL, 0);

    // 2) u = silu(conv(xz[:, :2048]) + conv_b)
    conv_silu_kernel<<<(MROWS * DINNER / 4 + 255) / 256, 256>>>(xz, conv_w, conv_b, u);

    // 3) xdbl = u @ W_xproj   (16-way deterministic split-K)
    xprojA<<<dim3(KSPLITS, MROWS / 64), 256>>>(u, W_xproj, xpart);
    xprojB<<<(MROWS * XPROJ_N + 255) / 256, 256>>>(xpart, xdbl);

    // 4+5) fused delta + selective scan -> yh (fp16)
    scan_kernel<<<dim3(DINNER / 16, BB), 256, SCAN_SMEM>>>(
        u, xz, xdbl, W_dt, b_dt, A_log, D_skip, yh);

    // 6) out = y @ W_out   [2048,2048]@[2048,1024], 2-way split-K + reduce
    gemm_mma<<<dim3(1024 / 128, MROWS / 128, 2), 256, GM_SMEM>>>(
        yh, woutTh, woutTl, part, DINNER, 1024, 1024,
        (size_t)MROWS * DMODEL);
    reduce2<<<(MROWS * DMODEL / 4 + 255) / 256, 256>>>(part, out, MROWS * DMODEL);
}

// round 16
// speedup vs baseline: 1.3948x; 1.0473x over previous
#include <cuda_runtime.h>
#include <cuda_fp16.h>
#include <cuda_bf16.h>
#include <math.h>
#include <cstdint>

// ---------------------------------------------------------------------------
// TemporalMamba: B=2, L=1024, D_MODEL=1024, D_INNER=2048, D_STATE=16,
// D_CONV=4, DT_RANK=64.
// Tensor cores via mma.sync.m16n8k16 fp16x2 split:
//   C = A(fp16) @ (Wh + Wl)^T.  Measured rel_err 3.6e-4 (gate 1e-3).
// Scan: cp.async double-buffered staging (hides per-chunk global latency).
// (toolchain is compute_100 base: tcgen05 unavailable)
// ---------------------------------------------------------------------------

#define BB       2
#define LL       1024
#define DMODEL   1024
#define DINNER   2048
#define DSTATE   16
#define DTRANK   64
#define MROWS    (BB * LL)                  // 2048
#define XPROJ_N  (DTRANK + 2 * DSTATE)      // 96
#define KSPLITS  16

// ------------------------- scratch (device globals) ------------------------
__device__ float g_xz[MROWS * 2 * DINNER];      // [M, 4096]
__device__ float g_u[MROWS * DINNER];           // [M, 2048]
__device__ float g_xdbl[MROWS * XPROJ_N];       // [M, 96]
__device__ float g_xpart[KSPLITS * MROWS * XPROJ_N];
__device__ float g_part[2 * MROWS * DMODEL];    // GEMM4 split-K partials

// fp16 operands
__device__ __half g_xh[MROWS * DMODEL];          // x fp16    [2048,1024]
__device__ __half g_winT_h[4096 * DMODEL];       // W_in^T hi [4096,1024]
__device__ __half g_winT_l[4096 * DMODEL];       //        lo
__device__ __half g_yh[MROWS * DINNER];          // y fp16    [2048,2048]
__device__ __half g_woutT_h[DMODEL * DINNER];    // W_out^T hi [1024,2048]
__device__ __half g_woutT_l[DMODEL * DINNER];

// ---------------------------------------------------------------------------
// mma.sync / ldmatrix / cp.async helpers
// ---------------------------------------------------------------------------
__device__ __forceinline__ uint32_t smem_u32(const void* p) {
    uint32_t a;
    asm("{ .reg .u64 t; cvta.to.shared.u64 t, %1; cvt.u32.u64 %0, t; }" : "=r"(a) : "l"(p));
    return a;
}
__device__ __forceinline__ void cpa16(uint32_t s, const void* g) {
    asm volatile("cp.async.cg.shared.global [%0], [%1], 16;" :: "r"(s), "l"(g));
}
__device__ __forceinline__ void cpa4(uint32_t s, const void* g) {
    asm volatile("cp.async.ca.shared.global [%0], [%1], 4;" :: "r"(s), "l"(g));
}
__device__ __forceinline__ void ldsm4(uint32_t& r0, uint32_t& r1, uint32_t& r2, uint32_t& r3,
                                      uint32_t addr) {
    asm volatile("ldmatrix.sync.aligned.m8n8.x4.shared.b16 {%0,%1,%2,%3}, [%4];"
                 : "=r"(r0), "=r"(r1), "=r"(r2), "=r"(r3) : "r"(addr));
}
__device__ __forceinline__ void mma16816(float& c0, float& c1, float& c2, float& c3,
                                         uint32_t a0, uint32_t a1, uint32_t a2, uint32_t a3,
                                         uint32_t b0, uint32_t b1) {
    asm volatile(
        "mma.sync.aligned.m16n8k16.row.col.f32.f16.f16.f32 "
        "{%0,%1,%2,%3}, {%4,%5,%6,%7}, {%8,%9}, {%0,%1,%2,%3};"
        : "+f"(c0), "+f"(c1), "+f"(c2), "+f"(c3)
        : "r"(a0), "r"(a1), "r"(a2), "r"(a3), "r"(b0), "r"(b1));
}

// ---------------------------------------------------------------------------
// fp16x2 split tensor-core GEMM:  C[M,N] = A[M,K] @ (Bh+Bl)^T
//   A row-major fp16 [M][K], B as Bt[N][K] (K-major) fp16 hi/lo.
//   CTA: 256 thr = 8 warps (2 M x 4 N), tile 128x128, warp 64x32, BK=64,
//   cp.async double buffer (3 tiles/stage, 110.6KB), 2 CTAs/SM.
//   gridDim.z splits K deterministically; z writes C + z*partStride.
// ---------------------------------------------------------------------------
#define SSTR     72                                  // smem row stride (fp16)
#define TILE_B   (128 * SSTR * 2)                    // 18432 B per tile
#define STAGE_B  (3 * TILE_B)                        // A, Bh, Bl = 55296 B
#define GM_SMEM  (2 * STAGE_B)                       // 110592 B

__device__ __forceinline__ void load_stage_tile(
    const __half* __restrict__ G, int rowBase, int k0, int K,
    uint32_t sdst, int tid)
{
#pragma unroll
    for (int i = 0; i < 4; i++) {
        int idx = tid + i * 256;            // 0..1023
        int r = idx >> 3;                   // row 0..127
        int q = idx & 7;                    // 16B chunk in 128B row
        const void* g = G + (size_t)(rowBase + r) * K + k0 + q * 8;
        cpa16(sdst + (uint32_t)(r * SSTR + q * 8) * 2, g);
    }
}

__global__ __launch_bounds__(256, 2)
void gemm_mma(const __half* __restrict__ A,
              const __half* __restrict__ Bh, const __half* __restrict__ Bl,
              float* __restrict__ C, int Kfull, int ldc, int kdepth,
              size_t partStride)
{
    extern __shared__ __align__(16) char dsm[];
    const uint32_t sbase = smem_u32(dsm);

    const int tid  = threadIdx.x;
    const int wid  = tid >> 5;
    const int lane = tid & 31;
    const int wm   = wid >> 2;              // 0..1  (M)
    const int wn   = wid & 3;               // 0..3  (N)
    const int bx   = blockIdx.x, by = blockIdx.y;
    const int kbase = blockIdx.z * kdepth;
    C += (size_t)blockIdx.z * partStride;

    const int aRow  = lane & 15;
    const int aCsel = (lane >> 4) * 8;
    const int bRow  = (lane & 7) + ((lane >> 4) << 3);
    const int bCsel = ((lane >> 3) & 1) * 8;

    float acc[4][4][4];
#pragma unroll
    for (int i = 0; i < 4; i++)
#pragma unroll
        for (int j = 0; j < 4; j++)
#pragma unroll
            for (int v = 0; v < 4; v++) acc[i][j][v] = 0.f;

    const int NC = kdepth >> 6;

    load_stage_tile(A,  by * 128, kbase, Kfull, sbase + 0 * TILE_B, tid);
    load_stage_tile(Bh, bx * 128, kbase, Kfull, sbase + 1 * TILE_B, tid);
    load_stage_tile(Bl, bx * 128, kbase, Kfull, sbase + 2 * TILE_B, tid);
    asm volatile("cp.async.commit_group;");

    for (int c = 0; c < NC; c++) {
        if (c + 1 < NC) {
            const uint32_t sd = sbase + ((c + 1) & 1) * STAGE_B;
            const int k0 = kbase + ((c + 1) << 6);
            load_stage_tile(A,  by * 128, k0, Kfull, sd + 0 * TILE_B, tid);
            load_stage_tile(Bh, bx * 128, k0, Kfull, sd + 1 * TILE_B, tid);
            load_stage_tile(Bl, bx * 128, k0, Kfull, sd + 2 * TILE_B, tid);
            asm volatile("cp.async.commit_group;");
            asm volatile("cp.async.wait_group 1;");
        } else {
            asm volatile("cp.async.wait_group 0;");
        }
        __syncthreads();

        const uint32_t st  = sbase + (c & 1) * STAGE_B;
        const uint32_t sA  = st;
        const uint32_t sBh = st + 1 * TILE_B;
        const uint32_t sBl = st + 2 * TILE_B;

#pragma unroll
        for (int kk = 0; kk < 64; kk += 16) {
            uint32_t a[4][4], bh[2][4], bl[2][4];
#pragma unroll
            for (int i = 0; i < 4; i++) {
                uint32_t off = (uint32_t)((wm * 64 + i * 16 + aRow) * SSTR + kk + aCsel) * 2;
                ldsm4(a[i][0], a[i][1], a[i][2], a[i][3], sA + off);
            }
#pragma unroll
            for (int j2 = 0; j2 < 2; j2++) {
                uint32_t off = (uint32_t)((wn * 32 + j2 * 16 + bRow) * SSTR + kk + bCsel) * 2;
                ldsm4(bh[j2][0], bh[j2][1], bh[j2][2], bh[j2][3], sBh + off);
            }
#pragma unroll
            for (int j2 = 0; j2 < 2; j2++) {
                uint32_t off = (uint32_t)((wn * 32 + j2 * 16 + bRow) * SSTR + kk + bCsel) * 2;
                ldsm4(bl[j2][0], bl[j2][1], bl[j2][2], bl[j2][3], sBl + off);
            }
            // A * Bh
#pragma unroll
            for (int i = 0; i < 4; i++)
#pragma unroll
                for (int j = 0; j < 4; j++) {
                    const uint32_t* b = bh[j >> 1] + (j & 1) * 2;
                    mma16816(acc[i][j][0], acc[i][j][1], acc[i][j][2], acc[i][j][3],
                             a[i][0], a[i][1], a[i][2], a[i][3], b[0], b[1]);
                }
            // A * Bl
#pragma unroll
            for (int i = 0; i < 4; i++)
#pragma unroll
                for (int j = 0; j < 4; j++) {
                    const uint32_t* b = bl[j >> 1] + (j & 1) * 2;
                    mma16816(acc[i][j][0], acc[i][j][1], acc[i][j][2], acc[i][j][3],
                             a[i][0], a[i][1], a[i][2], a[i][3], b[0], b[1]);
                }
        }
        __syncthreads();
    }

    const int mBase = by * 128 + wm * 64;
    const int nBase = bx * 128 + wn * 32;
    const int r0 = lane >> 2;
    const int c0 = (lane & 3) * 2;
#pragma unroll
    for (int i = 0; i < 4; i++) {
#pragma unroll
        for (int j = 0; j < 4; j++) {
            float* p0 = C + (size_t)(mBase + i * 16 + r0) * ldc + nBase + j * 8 + c0;
            *(float2*)p0                     = make_float2(acc[i][j][0], acc[i][j][1]);
            *(float2*)(p0 + (size_t)8 * ldc) = make_float2(acc[i][j][2], acc[i][j][3]);
        }
    }
}

// fixed-order split-K reduce: out = part[0..n) + part[n..2n)  (float4)
__global__ __launch_bounds__(256)
void reduce2(const float* __restrict__ part, float* __restrict__ out, int n)
{
    int i = (blockIdx.x * 256 + threadIdx.x) * 4;
    if (i >= n) return;
    float4 a = *(const float4*)(part + i);
    float4 b = *(const float4*)(part + (size_t)n + i);
    float4 r = make_float4(a.x + b.x, a.y + b.y, a.z + b.z, a.w + b.w);
    *(float4*)(out + i) = r;
}

// ---------------------------------------------------------------------------
// fp32 -> fp16 convert (row-major, float4 vectorized)
// ---------------------------------------------------------------------------
__global__ __launch_bounds__(256)
void conv_fp16(const float* __restrict__ in, __half* __restrict__ out, int n4)
{
    int i = blockIdx.x * 256 + threadIdx.x;
    if (i >= n4) return;
    float4 v = *(const float4*)(in + i * 4);
    __half2* p = (__half2*)(out + i * 4);
    p[0] = __half2(__float2half(v.x), __float2half(v.y));
    p[1] = __half2(__float2half(v.z), __float2half(v.w));
}

// transpose + fp16 hi/lo split:  in[K][N] fp32  ->  hiT/loT [N][K] fp16
__global__ __launch_bounds__(256)
void tsplit_fp16(const float* __restrict__ in,
                 __half* __restrict__ hiT, __half* __restrict__ loT,
                 int K, int N)
{
    __shared__ float t[32][33];
    int tx = threadIdx.x & 31;
    int ty = threadIdx.x >> 5;
    int n0 = blockIdx.x * 32;
    int k0 = blockIdx.y * 32;
#pragma unroll
    for (int j = 0; j < 4; j++) {
        int kk = ty + j * 8;
        t[kk][tx] = in[(size_t)(k0 + kk) * N + n0 + tx];
    }
    __syncthreads();
#pragma unroll
    for (int j = 0; j < 4; j++) {
        int a = ty + j * 8;
        float v = t[tx][a];
        __half h = __float2half(v);
        hiT[(size_t)(n0 + a) * K + k0 + tx] = h;
        loT[(size_t)(n0 + a) * K + k0 + tx] = __float2half(v - __half2float(h));
    }
}

// ---------------------------------------------------------------------------
// depthwise conv(4) + bias + silu, float4-vectorized over channels
// ---------------------------------------------------------------------------
__global__ __launch_bounds__(256)
void conv_silu_kernel(const float* __restrict__ xz,
                      const float* __restrict__ cw,
                      const float* __restrict__ cb,
                      float* __restrict__ u)
{
    int idx = blockIdx.x * blockDim.x + threadIdx.x;
    if (idx >= MROWS * DINNER / 4) return;
    int d4  = (idx & (DINNER / 4 - 1)) * 4;
    int row = idx >> 9;
    int l   = row & (LL - 1);

    float4 w0 = *(const float4*)(cw + d4 * 4 + 0);
    float4 w1 = *(const float4*)(cw + d4 * 4 + 4);
    float4 w2 = *(const float4*)(cw + d4 * 4 + 8);
    float4 w3 = *(const float4*)(cw + d4 * 4 + 12);
    float4 bias = *(const float4*)(cb + d4);

    const float* base = xz + (size_t)row * (2 * DINNER) + d4;
    const int stride = 2 * DINNER;

    float4 s = bias;
    if (l >= 3) {
        float4 v = *(const float4*)(base - 3 * stride);
        s.x += v.x * w0.x; s.y += v.y * w1.x; s.z += v.z * w2.x; s.w += v.w * w3.x;
    }
    if (l >= 2) {
        float4 v = *(const float4*)(base - 2 * stride);
        s.x += v.x * w0.y; s.y += v.y * w1.y; s.z += v.z * w2.y; s.w += v.w * w3.y;
    }
    if (l >= 1) {
        float4 v = *(const float4*)(base - 1 * stride);
        s.x += v.x * w0.z; s.y += v.y * w1.z; s.z += v.z * w2.z; s.w += v.w * w3.z;
    }
    {
        float4 v = *(const float4*)(base);
        s.x += v.x * w0.w; s.y += v.y * w1.w; s.z += v.z * w2.w; s.w += v.w * w3.w;
    }
    float4 r;
    r.x = s.x / (1.f + expf(-s.x));
    r.y = s.y / (1.f + expf(-s.y));
    r.z = s.z / (1.f + expf(-s.z));
    r.w = s.w / (1.f + expf(-s.w));
    *(float4*)(u + (size_t)row * DINNER + d4) = r;
}

// ---------------------------------------------------------------------------
// xproj split-K (16-way):  part[ks] = u[:, ks*128:(ks+1)*128] @ W_xproj[...]
// ---------------------------------------------------------------------------
#define XKD (DINNER / KSPLITS)             // 128 K per split
__global__ __launch_bounds__(256)
void xprojA(const float* __restrict__ u, const float* __restrict__ W,
            float* __restrict__ part)
{
    __shared__ float As[64 * 32];
    __shared__ float Bs[96 * 36];

    const int ks = blockIdx.x;
    const int mb = blockIdx.y;
    const int tid = threadIdx.x;
    const int rg = tid >> 4;
    const int cg = tid & 15;

    float acc[4][6];
#pragma unroll
    for (int r = 0; r < 4; r++)
#pragma unroll
        for (int j = 0; j < 6; j++) acc[r][j] = 0.f;

    for (int kc = 0; kc < XKD / 32; kc++) {
        const int kbase = ks * XKD + kc * 32;
#pragma unroll
        for (int i = tid; i < 64 * 32; i += 256) {
            int r = i >> 5, k = i & 31;
            As[r * 32 + k] = u[(size_t)(mb * 64 + r) * DINNER + kbase + k];
        }
#pragma unroll
        for (int i = tid; i < 96 * 32; i += 256) {
            int c = i % 96, k = i / 96;
            Bs[c * 36 + k] = W[(size_t)(kbase + k) * XPROJ_N + c];
        }
        __syncthreads();
#pragma unroll
        for (int kq = 0; kq < 8; kq++) {
            float4 a[4], b[6];
#pragma unroll
            for (int r = 0; r < 4; r++)
                a[r] = *(const float4*)&As[(rg * 4 + r) * 32 + kq * 4];
#pragma unroll
            for (int j = 0; j < 6; j++)
                b[j] = *(const float4*)&Bs[(j * 16 + cg) * 36 + kq * 4];
#pragma unroll
            for (int r = 0; r < 4; r++)
#pragma unroll
                for (int j = 0; j < 6; j++)
                    acc[r][j] += a[r].x * b[j].x + a[r].y * b[j].y
                               + a[r].z * b[j].z + a[r].w * b[j].w;
        }
        __syncthreads();
    }
#pragma unroll
    for (int r = 0; r < 4; r++)
#pragma unroll
        for (int j = 0; j < 6; j++)
            part[((size_t)ks * MROWS + mb * 64 + rg * 4 + r) * XPROJ_N + j * 16 + cg]
                = acc[r][j];
}

__global__ __launch_bounds__(256)
void xprojB(const float* __restrict__ part, float* __restrict__ xdbl)
{
    int idx = blockIdx.x * 256 + threadIdx.x;
    if (idx >= MROWS * XPROJ_N) return;
    float s = 0.f;
#pragma unroll
    for (int ks = 0; ks < KSPLITS; ks++)
        s += part[(size_t)ks * MROWS * XPROJ_N + idx];
    xdbl[idx] = s;
}

// ---------------------------------------------------------------------------
// selective scan with cp.async DOUBLE-BUFFERED staging:
//   prefetch chunk c+1's tiles while computing chunk c -> staging latency
//   hidden.  Same arithmetic as R8/R15 scan (bit-identical output).
// Chunk = 32 timesteps.  Dynamic smem 73856 B (3 CTAs/SM).
// ---------------------------------------------------------------------------
#define SCT 32
// persistent (floats)
#define OFF_W     0                        // [64][16]  1024
#define OFF_BD    1024                     // [16]
#define OFF_DSK   1040                     // [16]
// staging buffers x2, each 4096 floats:
#define OFF_STG   1056
#define STG_DT    0                        // [32][64]  2048
#define STG_U     2048                     // [32][16]  512
#define STG_Z     2560                     // [32][16]  512
#define STG_B     3072                     // [32][16]  512
#define STG_C     3584                     // [32][16]  512
#define STG_SIZE  4096
// scratch
#define OFF_DEL   (OFF_STG + 2 * STG_SIZE)         // 9248, 512
#define OFF_P     (OFF_DEL + 512)                  // 9760, [32][16][17] 8704
#define SCAN_SMEM ((OFF_P + 8704) * 4)             // 73856 bytes

__global__ __launch_bounds__(256)
void scan_kernel(const float* __restrict__ u,
                 const float* __restrict__ xz,
                 const float* __restrict__ xdbl,
                 const float* __restrict__ W_dt,   // [64, 2048]
                 const float* __restrict__ b_dt,   // [2048]
                 const float* __restrict__ A_log,
                 const float* __restrict__ Dskip,
                 __half* __restrict__ yh)
{
    extern __shared__ float sm[];
    float* sW   = sm + OFF_W;
    float* sbd  = sm + OFF_BD;
    float* sdsk = sm + OFF_DSK;
    float* sDel = sm + OFF_DEL;
    float* sP   = sm + OFF_P;
    const uint32_t smb = smem_u32(sm);     // byte base

    const int tid = threadIdx.x;
    const int tn = tid & 15;
    const int td = tid >> 4;
    const int dbase = blockIdx.x * 16;
    const int b = blockIdx.y;

    for (int i = tid; i < 64 * 16; i += 256) {
        int r = i >> 4, c = i & 15;
        sW[i] = W_dt[(size_t)r * DINNER + dbase + c];
    }
    if (tid < 16) {
        sbd[tid]  = b_dt[dbase + tid];
        sdsk[tid] = Dskip[dbase + tid];
    }
    const float Aq = -expf(A_log[(dbase + td) * DSTATE + tn]);

    // ---- stage one chunk into buffer `buf` via cp.async ----
    auto stage = [&](int buf, int t0) {
        const uint32_t sb = smb + (uint32_t)(OFF_STG + buf * STG_SIZE) * 4;
#pragma unroll
        for (int i = tid; i < SCT * 16; i += 256) {     // 2 iters
            int r = i >> 4, c = i & 15;
            int row = b * LL + t0 + r;
            cpa4(sb + (uint32_t)(STG_U + i) * 4, u    + (size_t)row * DINNER + dbase + c);
            cpa4(sb + (uint32_t)(STG_Z + i) * 4, xz   + (size_t)row * (2 * DINNER) + DINNER + dbase + c);
            cpa4(sb + (uint32_t)(STG_B + i) * 4, xdbl + (size_t)row * XPROJ_N + DTRANK + c);
            cpa4(sb + (uint32_t)(STG_C + i) * 4, xdbl + (size_t)row * XPROJ_N + DTRANK + DSTATE + c);
        }
#pragma unroll
        for (int i = tid; i < SCT * 64; i += 256) {     // 8 iters
            int r = i >> 6, k = i & 63;
            cpa4(sb + (uint32_t)(STG_DT + i) * 4,
                 xdbl + (size_t)(b * LL + t0 + r) * XPROJ_N + k);
        }
        asm volatile("cp.async.commit_group;");
    };

    stage(0, 0);
    __syncthreads();    // also covers sW/sbd init

    float h = 0.f;
    const int NCH = LL / SCT;              // 32 chunks

    for (int c = 0; c < NCH; c++) {
        if (c + 1 < NCH) {
            stage((c + 1) & 1, (c + 1) * SCT);
            asm volatile("cp.async.wait_group 1;");
        } else {
            asm volatile("cp.async.wait_group 0;");
        }
        __syncthreads();

        float* sDT = sm + OFF_STG + (c & 1) * STG_SIZE + STG_DT;
        float* sU  = sm + OFF_STG + (c & 1) * STG_SIZE + STG_U;
        float* sZ  = sm + OFF_STG + (c & 1) * STG_SIZE + STG_Z;
        float* sB  = sm + OFF_STG + (c & 1) * STG_SIZE + STG_B;
        float* sC  = sm + OFF_STG + (c & 1) * STG_SIZE + STG_C;
        const int t0 = c * SCT;

        // ---- fused delta (2 outputs/thread; rows r0 and r0+16) ----
        {
            const int cc = tid & 15;
            const int r0 = tid >> 4;
            float s0 = sbd[cc], s1 = sbd[cc];
#pragma unroll 8
            for (int k = 0; k < 64; k++) {
                float w = sW[k * 16 + cc];
                s0 += sDT[r0 * 64 + k] * w;
                s1 += sDT[(r0 + 16) * 64 + k] * w;
            }
            sDel[r0 * 16 + cc]        = (s0 > 20.f) ? s0 : log1pf(expf(s0));
            sDel[(r0 + 16) * 16 + cc] = (s1 > 20.f) ? s1 : log1pf(expf(s1));
        }
        __syncthreads();

        // ---- serial recurrence: critical path = 1 FFMA/step ----
#pragma unroll 8
        for (int tt = 0; tt < SCT; tt++) {
            float dlt = sDel[tt * 16 + td];
            float uu  = sU[tt * 16 + td];
            float bb  = sB[tt * 16 + tn];
            float cc2 = sC[tt * 16 + tn];
            float dA  = __expf(dlt * Aq);
            h = dA * h + (dlt * uu) * bb;
            sP[(tt * 16 + td) * 17 + tn] = h * cc2;
        }
        __syncthreads();

        // ---- parallel reduce over n + gate + fp16 output ----
#pragma unroll
        for (int v = 0; v < 2; v++) {
            int o = tid + v * 256;
            int tt = o >> 4, cc = o & 15;
            const float* p = sP + (tt * 16 + cc) * 17;
            float s = 0.f;
#pragma unroll
            for (int n = 0; n < 16; n++) s += p[n];
            float uu = sU[tt * 16 + cc];
            float zz = sZ[tt * 16 + cc];
            float yv = s + sdsk[cc] * uu;
            yv *= zz / (1.f + expf(-zz));
            int row = b * LL + t0 + tt;
            yh[(size_t)row * DINNER + dbase + cc] = __float2half(yv);
        }
        __syncthreads();
    }
}

// ---------------------------------------------------------------------------
extern "C" void kernel_launch(void* const* d_in, const int* in_sizes, int n_in,
                              void* d_out, int out_size)
{
    const float* x       = (const float*)d_in[0];  // [2,1024,1024]
    const float* W_in    = (const float*)d_in[1];  // [1024, 4096]
    const float* conv_w  = (const float*)d_in[2];  // [2048, 1, 4]
    const float* conv_b  = (const float*)d_in[3];  // [2048]
    const float* W_xproj = (const float*)d_in[4];  // [2048, 96]
    const float* W_dt    = (const float*)d_in[5];  // [64, 2048]
    const float* b_dt    = (const float*)d_in[6];  // [2048]
    const float* A_log   = (const float*)d_in[7];  // [2048, 16]
    const float* D_skip  = (const float*)d_in[8];  // [2048]
    const float* W_out   = (const float*)d_in[9];  // [2048, 1024]
    float* out = (float*)d_out;                    // [2,1024,1024]

    float* xz;    cudaGetSymbolAddress((void**)&xz,    g_xz);
    float* u;     cudaGetSymbolAddress((void**)&u,     g_u);
    float* xdbl;  cudaGetSymbolAddress((void**)&xdbl,  g_xdbl);
    float* xpart; cudaGetSymbolAddress((void**)&xpart, g_xpart);
    float* part;  cudaGetSymbolAddress((void**)&part,  g_part);

    __half *xh, *winTh, *winTl, *yh, *woutTh, *woutTl;
    cudaGetSymbolAddress((void**)&xh,     g_xh);
    cudaGetSymbolAddress((void**)&winTh,  g_winT_h);
    cudaGetSymbolAddress((void**)&winTl,  g_winT_l);
    cudaGetSymbolAddress((void**)&yh,     g_yh);
    cudaGetSymbolAddress((void**)&woutTh, g_woutT_h);
    cudaGetSymbolAddress((void**)&woutTl, g_woutT_l);

    cudaFuncSetAttribute(gemm_mma, cudaFuncAttributeMaxDynamicSharedMemorySize, GM_SMEM);
    cudaFuncSetAttribute(scan_kernel, cudaFuncAttributeMaxDynamicSharedMemorySize, SCAN_SMEM);

    // operand conversions
    conv_fp16<<<(MROWS * DMODEL / 4) / 256, 256>>>(x, xh, MROWS * DMODEL / 4);
    tsplit_fp16<<<dim3(4096 / 32, DMODEL / 32), 256>>>(W_in, winTh, winTl, DMODEL, 4096);
    tsplit_fp16<<<dim3(DMODEL / 32, DINNER / 32), 256>>>(W_out, woutTh, woutTl, DINNER, DMODEL);

    // 1) xz = x @ W_in        [2048,1024] @ [1024,4096]   (tensor cores)
    gemm_mma<<<dim3(4096 / 128, MROWS / 128, 1), 256, GM_SMEM>>>(
        xh, winTh, winTl, xz, DMODEL, 4096, DMODEL, 0);

    // 2) u = silu(conv(xz[:, :2048]) + conv_b)
    conv_silu_kernel<<<(MROWS * DINNER / 4 + 255) / 256, 256>>>(xz, conv_w, conv_b, u);

    // 3) xdbl = u @ W_xproj   (16-way deterministic split-K)
    xprojA<<<dim3(KSPLITS, MROWS / 64), 256>>>(u, W_xproj, xpart);
    xprojB<<<(MROWS * XPROJ_N + 255) / 256, 256>>>(xpart, xdbl);

    // 4+5) fused delta + selective scan -> yh (fp16), cp.async staged
    scan_kernel<<<dim3(DINNER / 16, BB), 256, SCAN_SMEM>>>(
        u, xz, xdbl, W_dt, b_dt, A_log, D_skip, yh);

    // 6) out = y @ W_out   [2048,2048]@[2048,1024], 2-way split-K + reduce
    gemm_mma<<<dim3(1024 / 128, MROWS / 128, 2), 256, GM_SMEM>>>(
        yh, woutTh, woutTl, part, DINNER, 1024, 1024,
        (size_t)MROWS * DMODEL);
    reduce2<<<(MROWS * DMODEL / 4 + 255) / 256, 256>>>(part, out, MROWS * DMODEL);
}